// round 5
// baseline (speedup 1.0000x reference)
#include <cuda_runtime.h>
#include <cstdint>

#define NP 8192
#define NT 8192
#define CAP 256
#define ROWB 32768              // bytes per adj row (8192 floats)
#define DSMEM 68608

// ---- dynamic smem layout ----
// build phase:
#define OFF_BUF   0             // 2 x 32 KB row buffers
#define OFF_MBAR  65536         // 2 x 8 B mbarriers
#define OFF_CNT   65552         // int
#define OFF_LIST  65568         // CAP ints
// layer phases (reuse buffer region):
#define OFF_WP    0             // 2048 floats
#define OFF_WT    8192          // 2048 floats
#define OFF_WPA   16384         // 1024 floats
#define OFF_WTA   20480         // 1024 floats
#define OFF_BP    24576         // 64 floats
#define OFF_BT    24832         // 64 floats
#define OFF_AC    25088         // 32 floats
#define OFF_X     25344         // 8 warps x 128 floats
#define OFF_RED   29440         // 256 floats

// ---------------- static scratch ----------------
__device__ __align__(16) float d_pa[NP * 64];
__device__ __align__(16) float d_pb[NP * 64];
__device__ __align__(16) float d_ta[NT * 64];
__device__ __align__(16) float d_tb[NT * 64];
__device__ __align__(16) float d_prp[NT * 16];
__device__ __align__(16) float d_prt[NP * 16];
__device__ float d_lp[NP];
__device__ float d_logits[NT];
__device__ int d_rcnt[NP];
__device__ int d_ccnt[NT];      // zero-init; re-zeroed at end of every launch
__device__ int d_rlist[NP * CAP];
__device__ int d_clist[NT * CAP];
__device__ unsigned g_arrive = 0;
__device__ volatile unsigned g_gen = 0;

__device__ __forceinline__ uint32_t smem_u32(const void* p) {
    return (uint32_t)__cvta_generic_to_shared(p);
}

__device__ __forceinline__ void mbar_init(uint32_t mbar, int cnt) {
    asm volatile("mbarrier.init.shared::cta.b64 [%0], %1;" :: "r"(mbar), "r"(cnt) : "memory");
}
__device__ __forceinline__ void mbar_expect_tx(uint32_t mbar, int bytes) {
    asm volatile("mbarrier.arrive.expect_tx.shared::cta.b64 _, [%0], %1;" :: "r"(mbar), "r"(bytes) : "memory");
}
__device__ __forceinline__ void bulk_ld(uint32_t dst, const void* src, int bytes, uint32_t mbar) {
    asm volatile("cp.async.bulk.shared::cta.global.mbarrier::complete_tx::bytes [%0], [%1], %2, [%3];"
        :: "r"(dst), "l"(src), "r"(bytes), "r"(mbar) : "memory");
}
__device__ __forceinline__ void mbar_wait(uint32_t mbar, int phase) {
    asm volatile(
        "{\n\t.reg .pred P;\n"
        "W%=:\n\t"
        "mbarrier.try_wait.parity.acquire.cta.shared::cta.b64 P, [%0], %1, 0x989680;\n\t"
        "@P bra D%=;\n\t"
        "bra W%=;\n"
        "D%=:\n\t}"
        :: "r"(mbar), "r"(phase) : "memory");
}

// ---------------- grid-wide barrier ----------------
__device__ __forceinline__ void gbar(int nb, unsigned& gen) {
    __syncthreads();
    if (threadIdx.x == 0) {
        __threadfence();
        unsigned a = atomicAdd(&g_arrive, 1u);
        if (a == (unsigned)nb - 1u) {
            atomicExch(&g_arrive, 0u);
            __threadfence();
            g_gen = gen + 1u;
        } else {
            while (g_gen == gen) { __nanosleep(32); }
        }
    }
    gen += 1u;
    __syncthreads();
    __threadfence();
}

// ---------------- edge emit ----------------
__device__ __forceinline__ void emit_edge(int row, int j, int* scnt, int* slist) {
    int slot = atomicAdd(scnt, 1);
    if (slot < CAP) slist[slot] = j;
    int cs = atomicAdd(&d_ccnt[j], 1);
    if (cs < CAP) d_clist[j * CAP + cs] = row;
}

// ---------------- direct layer: out = relu([self|agg] @ W + B) ----------------
template <int IN, int OUT, bool SELF_FIRST>
__device__ __forceinline__ void layer_node(
    int node, const float* __restrict__ self_f, const float* __restrict__ other_f,
    const int* __restrict__ cnt, const int* __restrict__ list,
    const float* sW, const float* sB, float* __restrict__ out_f,
    float* xs, int lane)
{
    constexpr int C = 2 * IN;
    constexpr int SOFF = SELF_FIRST ? 0 : IN;
    constexpr int AOFF = SELF_FIRST ? IN : 0;
#pragma unroll
    for (int k = lane; k < IN; k += 32) xs[SOFF + k] = self_f[node * IN + k];

    constexpr int V = IN / 4;
    constexpr int G = 32 / V;
    int v = lane % V, g = lane / V;
    float4 acc = make_float4(0.f, 0.f, 0.f, 0.f);
    int n = min(cnt[node], CAP);
    const int* lst = list + node * CAP;
    for (int e = g; e < n; e += G) {
        float4 t4 = *reinterpret_cast<const float4*>(other_f + lst[e] * IN + v * 4);
        acc.x += t4.x; acc.y += t4.y; acc.z += t4.z; acc.w += t4.w;
    }
#pragma unroll
    for (int d = G / 2; d > 0; d >>= 1) {
        acc.x += __shfl_down_sync(0xffffffffu, acc.x, d * V);
        acc.y += __shfl_down_sync(0xffffffffu, acc.y, d * V);
        acc.z += __shfl_down_sync(0xffffffffu, acc.z, d * V);
        acc.w += __shfl_down_sync(0xffffffffu, acc.w, d * V);
    }
    if (g == 0) *reinterpret_cast<float4*>(xs + AOFF + v * 4) = acc;
    __syncwarp();

    constexpr int JPL = (OUT + 31) / 32;
    if (lane < OUT) {
        float a[JPL];
#pragma unroll
        for (int jj = 0; jj < JPL; jj++) a[jj] = sB[lane + jj * 32];
#pragma unroll
        for (int k = 0; k < C; k++) {
            float xv = xs[k];
#pragma unroll
            for (int jj = 0; jj < JPL; jj++) a[jj] += xv * sW[k * OUT + lane + jj * 32];
        }
#pragma unroll
        for (int jj = 0; jj < JPL; jj++)
            out_f[node * OUT + lane + jj * 32] = fmaxf(a[jj], 0.f);
    }
    __syncwarp();
}

// ---------------- layer3 + fused 64->16 projection epilogue ----------------
template <bool SELF_FIRST>
__device__ __forceinline__ void layer3_proj_node(
    int node, const float* __restrict__ self_f, const float* __restrict__ other_f,
    const int* __restrict__ cnt, const int* __restrict__ list,
    const float* sW, const float* sB, const float* sWagg,
    float* __restrict__ out_f, float* __restrict__ proj_f,
    float* xs, int lane)
{
    constexpr int IN = 16, OUT = 64;
    constexpr int SOFF = SELF_FIRST ? 0 : IN;
    constexpr int AOFF = SELF_FIRST ? IN : 0;
#pragma unroll
    for (int k = lane; k < IN; k += 32) xs[SOFF + k] = self_f[node * IN + k];

    int v = lane & 3, g = lane >> 2;
    float4 acc = make_float4(0.f, 0.f, 0.f, 0.f);
    int n = min(cnt[node], CAP);
    const int* lst = list + node * CAP;
    for (int e = g; e < n; e += 8) {
        float4 t4 = *reinterpret_cast<const float4*>(other_f + lst[e] * IN + v * 4);
        acc.x += t4.x; acc.y += t4.y; acc.z += t4.z; acc.w += t4.w;
    }
#pragma unroll
    for (int d = 4; d > 0; d >>= 1) {
        acc.x += __shfl_down_sync(0xffffffffu, acc.x, d * 4);
        acc.y += __shfl_down_sync(0xffffffffu, acc.y, d * 4);
        acc.z += __shfl_down_sync(0xffffffffu, acc.z, d * 4);
        acc.w += __shfl_down_sync(0xffffffffu, acc.w, d * 4);
    }
    if (g == 0) *reinterpret_cast<float4*>(xs + AOFF + v * 4) = acc;
    __syncwarp();

    float a0 = sB[lane], a1 = sB[lane + 32];
#pragma unroll
    for (int k = 0; k < 32; k++) {
        float xv = xs[k];
        a0 += xv * sW[k * OUT + lane];
        a1 += xv * sW[k * OUT + lane + 32];
    }
    a0 = fmaxf(a0, 0.f); a1 = fmaxf(a1, 0.f);
    out_f[node * OUT + lane] = a0;
    out_f[node * OUT + lane + 32] = a1;
    xs[lane] = a0; xs[lane + 32] = a1;
    __syncwarp();

    if (lane < 16) {
        float pr = 0.f;
#pragma unroll
        for (int k = 0; k < 64; k++) pr += xs[k] * sWagg[k * 16 + lane];
        proj_f[node * 16 + lane] = pr;
    }
    __syncwarp();
}

// ---------------- L4 combine ----------------
__device__ __forceinline__ float l4_node(
    int node, const float* __restrict__ self_f, const float* __restrict__ proj_other,
    const int* __restrict__ cnt, const int* __restrict__ list,
    const float* sWself, const float* sB, const float* sWac,
    float* __restrict__ out_f, float* xs, int lane)
{
#pragma unroll
    for (int k = lane; k < 64; k += 32) xs[k] = self_f[node * 64 + k];

    int v = lane & 3, g = lane >> 2;
    float4 acc = make_float4(0.f, 0.f, 0.f, 0.f);
    int n = min(cnt[node], CAP);
    const int* lst = list + node * CAP;
    for (int e = g; e < n; e += 8) {
        float4 t4 = *reinterpret_cast<const float4*>(proj_other + lst[e] * 16 + v * 4);
        acc.x += t4.x; acc.y += t4.y; acc.z += t4.z; acc.w += t4.w;
    }
#pragma unroll
    for (int d = 4; d > 0; d >>= 1) {
        acc.x += __shfl_down_sync(0xffffffffu, acc.x, d * 4);
        acc.y += __shfl_down_sync(0xffffffffu, acc.y, d * 4);
        acc.z += __shfl_down_sync(0xffffffffu, acc.z, d * 4);
        acc.w += __shfl_down_sync(0xffffffffu, acc.w, d * 4);
    }
    if (g == 0) *reinterpret_cast<float4*>(xs + 64 + v * 4) = acc;
    __syncwarp();

    float contrib = 0.f;
    if (lane < 16) {
        float a = sB[lane] + xs[64 + lane];
#pragma unroll
        for (int k = 0; k < 64; k++) a += xs[k] * sWself[k * 16 + lane];
        float r = fmaxf(a, 0.f);
        out_f[node * 16 + lane] = r;
        contrib = r * sWac[lane];
    }
#pragma unroll
    for (int d = 16; d > 0; d >>= 1)
        contrib += __shfl_down_sync(0xffffffffu, contrib, d);
    __syncwarp();
    return contrib;   // valid in lane 0
}

// ---------------- the single persistent kernel ----------------
__global__ void __launch_bounds__(256, 3) fused_k(
    const float* __restrict__ p0, const float* __restrict__ t0, const float* __restrict__ adj,
    const float* __restrict__ wp1, const float* __restrict__ bp1,
    const float* __restrict__ wt1, const float* __restrict__ bt1,
    const float* __restrict__ wp2, const float* __restrict__ bp2,
    const float* __restrict__ wt2, const float* __restrict__ bt2,
    const float* __restrict__ wp3, const float* __restrict__ bp3,
    const float* __restrict__ wt3, const float* __restrict__ bt3,
    const float* __restrict__ wp4, const float* __restrict__ bp4,
    const float* __restrict__ wt4, const float* __restrict__ bt4,
    const float* __restrict__ wac, const float* __restrict__ bac,
    float* __restrict__ out, int nb)
{
    extern __shared__ __align__(128) char sm[];
    int tid = threadIdx.x, warp = tid >> 5, lane = tid & 31;
    unsigned gen = g_gen;
    int tw = nb * 8;
    int gw = blockIdx.x * 8 + warp;

    // ================= P1: TMA-streamed adjacency build =================
    {
        float4* buf = (float4*)(sm + OFF_BUF);
        uint32_t mb = smem_u32(sm + OFF_MBAR);
        uint32_t bufa = smem_u32(sm + OFF_BUF);
        int* scnt = (int*)(sm + OFF_CNT);
        int* slist = (int*)(sm + OFF_LIST);

        if (tid < 2) mbar_init(mb + tid * 8, 1);
        __syncthreads();

        int nIt = (blockIdx.x < NP) ? ((NP - 1 - blockIdx.x) / nb + 1) : 0;
        int ph0 = 0, ph1 = 0;
        if (nIt > 0 && tid == 0) {
            mbar_expect_tx(mb, ROWB);
            bulk_ld(bufa, (const char*)adj + (size_t)blockIdx.x * ROWB, ROWB, mb);
        }
        for (int i = 0; i < nIt; i++) {
            int st = i & 1;
            int row = blockIdx.x + i * nb;
            if (tid == 0) *scnt = 0;
            __syncthreads();                       // prev iter fully done; scnt reset visible
            if (tid == 0 && i + 1 < nIt) {         // refill the other buffer
                int st2 = st ^ 1;
                mbar_expect_tx(mb + st2 * 8, ROWB);
                bulk_ld(bufa + st2 * ROWB, (const char*)adj + (size_t)(row + nb) * ROWB, ROWB, mb + st2 * 8);
            }
            mbar_wait(mb + st * 8, st ? ph1 : ph0);
            if (st) ph1 ^= 1; else ph0 ^= 1;

            const float4* b = buf + st * 2048;
#pragma unroll
            for (int k = 0; k < 8; k++) {
                int idx = tid + k * 256;
                float4 v = b[idx];
                if (v.x != 0.f || v.y != 0.f || v.z != 0.f || v.w != 0.f) {
                    int jb = idx << 2;
                    if (v.x != 0.f) emit_edge(row, jb + 0, scnt, slist);
                    if (v.y != 0.f) emit_edge(row, jb + 1, scnt, slist);
                    if (v.z != 0.f) emit_edge(row, jb + 2, scnt, slist);
                    if (v.w != 0.f) emit_edge(row, jb + 3, scnt, slist);
                }
            }
            __syncthreads();                       // all emits done
            int n = min(*scnt, CAP);
            for (int e = tid; e < n; e += 256) d_rlist[row * CAP + e] = slist[e];
            if (tid == 0) d_rcnt[row] = n;
            __syncthreads();                       // lists consumed before next reset
        }
    }
    gbar(nb, gen);

    float* sWp  = (float*)(sm + OFF_WP);
    float* sWt  = (float*)(sm + OFF_WT);
    float* sWpA = (float*)(sm + OFF_WPA);
    float* sWtA = (float*)(sm + OFF_WTA);
    float* sBp  = (float*)(sm + OFF_BP);
    float* sBt  = (float*)(sm + OFF_BT);
    float* sAC  = (float*)(sm + OFF_AC);
    float* xs   = (float*)(sm + OFF_X) + warp * 128;
    float* sRed = (float*)(sm + OFF_RED);

    // ---- P2: layer 1 (8,8)->(8,8) ----
    for (int i = tid; i < 128; i += 256) { sWp[i] = wp1[i]; sWt[i] = wt1[i]; }
    if (tid < 8) { sBp[tid] = bp1[tid]; sBt[tid] = bt1[tid]; }
    __syncthreads();
    for (int idx = gw; idx < NP + NT; idx += tw) {
        if (idx < NP) layer_node<8, 8, true >(idx,      p0, t0, d_rcnt, d_rlist, sWp, sBp, d_pa, xs, lane);
        else          layer_node<8, 8, false>(idx - NP, t0, p0, d_ccnt, d_clist, sWt, sBt, d_ta, xs, lane);
    }
    gbar(nb, gen);

    // ---- P3: layer 2 (8,8)->(16,16) ----
    for (int i = tid; i < 256; i += 256) { sWp[i] = wp2[i]; sWt[i] = wt2[i]; }
    if (tid < 16) { sBp[tid] = bp2[tid]; sBt[tid] = bt2[tid]; }
    __syncthreads();
    for (int idx = gw; idx < NP + NT; idx += tw) {
        if (idx < NP) layer_node<8, 16, true >(idx,      d_pa, d_ta, d_rcnt, d_rlist, sWp, sBp, d_pb, xs, lane);
        else          layer_node<8, 16, false>(idx - NP, d_ta, d_pa, d_ccnt, d_clist, sWt, sBt, d_tb, xs, lane);
    }
    gbar(nb, gen);

    // ---- P4: layer 3 (16,16)->(64,64) + fused 64->16 projection ----
    for (int i = tid; i < 2048; i += 256) { sWp[i] = wp3[i]; sWt[i] = wt3[i]; }
    for (int i = tid; i < 1024; i += 256) { sWpA[i] = wp4[1024 + i]; sWtA[i] = wt4[i]; }
    if (tid < 64) { sBp[tid] = bp3[tid]; sBt[tid] = bt3[tid]; }
    __syncthreads();
    for (int idx = gw; idx < NP + NT; idx += tw) {
        if (idx < NP) layer3_proj_node<true >(idx,      d_pb, d_tb, d_rcnt, d_rlist, sWp, sBp, sWtA, d_pa, d_prt, xs, lane);
        else          layer3_proj_node<false>(idx - NP, d_tb, d_pb, d_ccnt, d_clist, sWt, sBt, sWpA, d_ta, d_prp, xs, lane);
    }
    gbar(nb, gen);

    // ---- P5: p-side L4 combine -> d_lp ----
    for (int i = tid; i < 1024; i += 256) { sWp[i] = wp4[i]; sWt[i] = wt4[1024 + i]; }
    if (tid < 16) { sBp[tid] = bp4[tid]; sBt[tid] = bt4[tid]; }
    if (tid < 32) sAC[tid] = wac[tid];
    __syncthreads();
    for (int idx = gw; idx < NP; idx += tw) {
        float c = l4_node(idx, d_pa, d_prp, d_rcnt, d_rlist, sWp, sBp, sAC, d_pb, xs, lane);
        if (lane == 0) d_lp[idx] = c;
    }
    gbar(nb, gen);

    // ---- P6: t-side L4 combine + logits ----
    {
        float bias = bac[0];
        for (int idx = gw; idx < NT; idx += tw) {
            float c = l4_node(idx, d_ta, d_prt, d_ccnt, d_clist, sWt, sBt, sAC + 16, d_tb, xs, lane);
            int n = min(d_ccnt[idx], CAP);
            const int* lst = d_clist + idx * CAP;
            float s = 0.f;
            for (int e = lane; e < n; e += 32) s += d_lp[lst[e]];
#pragma unroll
            for (int d = 16; d > 0; d >>= 1) s += __shfl_down_sync(0xffffffffu, s, d);
            if (lane == 0) d_logits[idx] = s + c + bias;
        }
    }
    gbar(nb, gen);

    // ---- P7: redundant per-block softmax reduction + write + re-zero ccnt ----
    {
        float m = -1e30f;
        for (int i = tid; i < NT; i += 256) m = fmaxf(m, d_logits[i]);
        sRed[tid] = m; __syncthreads();
        for (int s = 128; s > 0; s >>= 1) {
            if (tid < s) sRed[tid] = fmaxf(sRed[tid], sRed[tid + s]);
            __syncthreads();
        }
        float mx = sRed[0]; __syncthreads();
        float sum = 0.f;
        for (int i = tid; i < NT; i += 256) sum += __expf(d_logits[i] - mx);
        sRed[tid] = sum; __syncthreads();
        for (int s = 128; s > 0; s >>= 1) {
            if (tid < s) sRed[tid] += sRed[tid + s];
            __syncthreads();
        }
        float inv = 1.f / sRed[0];
        for (int i = blockIdx.x * 256 + tid; i < NT; i += nb * 256) {
            out[i] = __expf(d_logits[i] - mx) * inv;
            d_ccnt[i] = 0;     // reset for next launch
        }
    }
}

// ---------------- launch ----------------
extern "C" void kernel_launch(void* const* d_in, const int* in_sizes, int n_in,
                              void* d_out, int out_size) {
    const float* p    = (const float*)d_in[0];
    const float* t    = (const float*)d_in[1];
    const float* adj  = (const float*)d_in[2];
    const float* w_p1 = (const float*)d_in[3];  const float* b_p1 = (const float*)d_in[4];
    const float* w_t1 = (const float*)d_in[5];  const float* b_t1 = (const float*)d_in[6];
    const float* w_p2 = (const float*)d_in[7];  const float* b_p2 = (const float*)d_in[8];
    const float* w_t2 = (const float*)d_in[9];  const float* b_t2 = (const float*)d_in[10];
    const float* w_p3 = (const float*)d_in[11]; const float* b_p3 = (const float*)d_in[12];
    const float* w_t3 = (const float*)d_in[13]; const float* b_t3 = (const float*)d_in[14];
    const float* w_p4 = (const float*)d_in[15]; const float* b_p4 = (const float*)d_in[16];
    const float* w_t4 = (const float*)d_in[17]; const float* b_t4 = (const float*)d_in[18];
    const float* w_ac = (const float*)d_in[19]; const float* b_ac = (const float*)d_in[20];
    float* out = (float*)d_out;

    cudaFuncSetAttribute(fused_k, cudaFuncAttributeMaxDynamicSharedMemorySize, DSMEM);

    int dev = 0;
    cudaGetDevice(&dev);
    int sms = 0;
    cudaDeviceGetAttribute(&sms, cudaDevAttrMultiProcessorCount, dev);
    int bpm = 0;
    cudaOccupancyMaxActiveBlocksPerMultiprocessor(&bpm, fused_k, 256, DSMEM);
    if (bpm < 1) bpm = 1;
    if (bpm > 3) bpm = 3;
    int nb = sms * bpm;
    if (nb > NP) nb = NP;

    fused_k<<<nb, 256, DSMEM>>>(p, t, adj,
                                w_p1, b_p1, w_t1, b_t1,
                                w_p2, b_p2, w_t2, b_t2,
                                w_p3, b_p3, w_t3, b_t3,
                                w_p4, b_p4, w_t4, b_t4,
                                w_ac, b_ac, out, nb);
}

// round 6
// speedup vs baseline: 1.2789x; 1.2789x over previous
#include <cuda_runtime.h>

#define NP 8192
#define NT 8192
#define CAP 256
#define ROW_F4 (NT/4)

// ---------------- static scratch ----------------
__device__ __align__(16) float d_pa[NP * 64];
__device__ __align__(16) float d_pb[NP * 64];
__device__ __align__(16) float d_ta[NT * 64];
__device__ __align__(16) float d_tb[NT * 64];
__device__ __align__(16) float d_prp[NT * 16];   // t3 @ wp4_agg (for p-side L4)
__device__ __align__(16) float d_prt[NP * 16];   // p3 @ wt4_agg (for t-side L4)
__device__ float d_lp[NP];
__device__ float d_logits[NT];
__device__ int d_rcnt[NP];
__device__ int d_ccnt[NT];      // zero-init; re-zeroed by softmax kernel each launch
__device__ int d_rlist[NP * CAP];
__device__ int d_clist[NT * CAP];

// ---------------- build: block per row, 8 in-flight float4 loads per thread ----------------
__global__ void __launch_bounds__(256) build_k(const float* __restrict__ adj) {
    __shared__ int s_cnt;
    int row = blockIdx.x;
    if (threadIdx.x == 0) s_cnt = 0;
    __syncthreads();

    const float4* a4 = reinterpret_cast<const float4*>(adj) + (size_t)row * ROW_F4 + threadIdx.x;
    float4 v[8];
#pragma unroll
    for (int k = 0; k < 8; k++) v[k] = __ldcs(a4 + k * 256);

#pragma unroll
    for (int k = 0; k < 8; k++) {
        if (v[k].x != 0.f || v[k].y != 0.f || v[k].z != 0.f || v[k].w != 0.f) {
            int jb = (threadIdx.x + k * 256) << 2;
            float vals[4] = {v[k].x, v[k].y, v[k].z, v[k].w};
#pragma unroll
            for (int q = 0; q < 4; q++) {
                if (vals[q] != 0.f) {
                    int j = jb + q;
                    int slot = atomicAdd(&s_cnt, 1);
                    if (slot < CAP) d_rlist[row * CAP + slot] = j;
                    int cs = atomicAdd(&d_ccnt[j], 1);
                    if (cs < CAP) d_clist[j * CAP + cs] = row;
                }
            }
        }
    }
    __syncthreads();
    if (threadIdx.x == 0) d_rcnt[row] = min(s_cnt, CAP);
}

// ---------------- generic layer node ----------------
template <int IN, int OUT, bool SELF_FIRST>
__device__ __forceinline__ void layer_node(
    int node, const float* __restrict__ self_f, const float* __restrict__ other_f,
    const int* __restrict__ cnt, const int* __restrict__ list,
    const float* sW, const float* sB, float* __restrict__ out_f,
    float* xs, int lane)
{
    constexpr int C = 2 * IN;
    constexpr int SOFF = SELF_FIRST ? 0 : IN;
    constexpr int AOFF = SELF_FIRST ? IN : 0;
#pragma unroll
    for (int k = lane; k < IN; k += 32) xs[SOFF + k] = self_f[node * IN + k];

    constexpr int V = IN / 4;
    constexpr int G = 32 / V;
    int v = lane % V, g = lane / V;
    float4 acc = make_float4(0.f, 0.f, 0.f, 0.f);
    int n = min(cnt[node], CAP);
    const int* lst = list + node * CAP;
    for (int e = g; e < n; e += G) {
        float4 t4 = *reinterpret_cast<const float4*>(other_f + lst[e] * IN + v * 4);
        acc.x += t4.x; acc.y += t4.y; acc.z += t4.z; acc.w += t4.w;
    }
#pragma unroll
    for (int d = G / 2; d > 0; d >>= 1) {
        acc.x += __shfl_down_sync(0xffffffffu, acc.x, d * V);
        acc.y += __shfl_down_sync(0xffffffffu, acc.y, d * V);
        acc.z += __shfl_down_sync(0xffffffffu, acc.z, d * V);
        acc.w += __shfl_down_sync(0xffffffffu, acc.w, d * V);
    }
    if (g == 0) *reinterpret_cast<float4*>(xs + AOFF + v * 4) = acc;
    __syncwarp();

    constexpr int JPL = (OUT + 31) / 32;
    if (lane < OUT) {
        float a[JPL];
#pragma unroll
        for (int jj = 0; jj < JPL; jj++) a[jj] = sB[lane + jj * 32];
#pragma unroll
        for (int k = 0; k < C; k++) {
            float xv = xs[k];
#pragma unroll
            for (int jj = 0; jj < JPL; jj++) a[jj] += xv * sW[k * OUT + lane + jj * 32];
        }
#pragma unroll
        for (int jj = 0; jj < JPL; jj++)
            out_f[node * OUT + lane + jj * 32] = fmaxf(a[jj], 0.f);
    }
}

// ---------------- merged L1 kernel ----------------
__global__ void __launch_bounds__(256) l1_k(
    const float* __restrict__ p0, const float* __restrict__ t0,
    const float* __restrict__ wp, const float* __restrict__ bp,
    const float* __restrict__ wt, const float* __restrict__ bt)
{
    __shared__ float sWp[128], sWt[128], sBp[8], sBt[8];
    __shared__ __align__(16) float sX[8][16];
    int tid = threadIdx.x, warp = tid >> 5, lane = tid & 31;
    if (tid < 128) { sWp[tid] = wp[tid]; sWt[tid] = wt[tid]; }
    else if (tid < 136) sBp[tid - 128] = bp[tid - 128];
    else if (tid < 144) sBt[tid - 136] = bt[tid - 136];
    __syncthreads();
    int idx = blockIdx.x * 8 + warp;
    if (idx < NP) layer_node<8, 8, true >(idx,      p0, t0, d_rcnt, d_rlist, sWp, sBp, d_pa, sX[warp], lane);
    else          layer_node<8, 8, false>(idx - NP, t0, p0, d_ccnt, d_clist, sWt, sBt, d_ta, sX[warp], lane);
}

// ---------------- merged L2 kernel ----------------
__global__ void __launch_bounds__(256) l2_k(
    const float* __restrict__ wp, const float* __restrict__ bp,
    const float* __restrict__ wt, const float* __restrict__ bt)
{
    __shared__ float sWp[256], sWt[256], sBp[16], sBt[16];
    __shared__ __align__(16) float sX[8][16];
    int tid = threadIdx.x, warp = tid >> 5, lane = tid & 31;
    sWp[tid] = wp[tid]; sWt[tid] = wt[tid];
    if (tid < 16) sBp[tid] = bp[tid];
    else if (tid < 32) sBt[tid - 16] = bt[tid - 16];
    __syncthreads();
    int idx = blockIdx.x * 8 + warp;
    if (idx < NP) layer_node<8, 16, true >(idx,      d_pa, d_ta, d_rcnt, d_rlist, sWp, sBp, d_pb, sX[warp], lane);
    else          layer_node<8, 16, false>(idx - NP, d_ta, d_pa, d_ccnt, d_clist, sWt, sBt, d_tb, sX[warp], lane);
}

// ---------------- L3 + fused 64->16 projection ----------------
template <bool SELF_FIRST>
__device__ __forceinline__ void layer3_proj_node(
    int node, const float* __restrict__ self_f, const float* __restrict__ other_f,
    const int* __restrict__ cnt, const int* __restrict__ list,
    const float* sW, const float* sB, const float* sWagg,
    float* __restrict__ out_f, float* __restrict__ proj_f,
    float* xs, int lane)
{
    constexpr int IN = 16, OUT = 64;
    constexpr int SOFF = SELF_FIRST ? 0 : IN;
    constexpr int AOFF = SELF_FIRST ? IN : 0;
#pragma unroll
    for (int k = lane; k < IN; k += 32) xs[SOFF + k] = self_f[node * IN + k];

    int v = lane & 3, g = lane >> 2;
    float4 acc = make_float4(0.f, 0.f, 0.f, 0.f);
    int n = min(cnt[node], CAP);
    const int* lst = list + node * CAP;
    for (int e = g; e < n; e += 8) {
        float4 t4 = *reinterpret_cast<const float4*>(other_f + lst[e] * IN + v * 4);
        acc.x += t4.x; acc.y += t4.y; acc.z += t4.z; acc.w += t4.w;
    }
#pragma unroll
    for (int d = 4; d > 0; d >>= 1) {
        acc.x += __shfl_down_sync(0xffffffffu, acc.x, d * 4);
        acc.y += __shfl_down_sync(0xffffffffu, acc.y, d * 4);
        acc.z += __shfl_down_sync(0xffffffffu, acc.z, d * 4);
        acc.w += __shfl_down_sync(0xffffffffu, acc.w, d * 4);
    }
    if (g == 0) *reinterpret_cast<float4*>(xs + AOFF + v * 4) = acc;
    __syncwarp();

    float a0 = sB[lane], a1 = sB[lane + 32];
#pragma unroll
    for (int k = 0; k < 32; k++) {
        float xv = xs[k];
        a0 += xv * sW[k * OUT + lane];
        a1 += xv * sW[k * OUT + lane + 32];
    }
    a0 = fmaxf(a0, 0.f); a1 = fmaxf(a1, 0.f);
    out_f[node * OUT + lane] = a0;
    out_f[node * OUT + lane + 32] = a1;
    xs[lane] = a0; xs[lane + 32] = a1;
    __syncwarp();

    if (lane < 16) {
        float pr = 0.f;
#pragma unroll
        for (int k = 0; k < 64; k++) pr += xs[k] * sWagg[k * 16 + lane];
        proj_f[node * 16 + lane] = pr;
    }
}

__global__ void __launch_bounds__(256) l3_k(
    const float* __restrict__ wp3, const float* __restrict__ bp3,
    const float* __restrict__ wt3, const float* __restrict__ bt3,
    const float* __restrict__ wp4, const float* __restrict__ wt4)
{
    __shared__ float sWp[2048], sWt[2048], sWpA[1024], sWtA[1024], sBp[64], sBt[64];
    __shared__ __align__(16) float sX[8][128];
    int tid = threadIdx.x, warp = tid >> 5, lane = tid & 31;
    for (int i = tid; i < 2048; i += 256) { sWp[i] = wp3[i]; sWt[i] = wt3[i]; }
    for (int i = tid; i < 1024; i += 256) { sWpA[i] = wp4[1024 + i]; sWtA[i] = wt4[i]; }
    if (tid < 64) { sBp[tid] = bp3[tid]; sBt[tid] = bt3[tid]; }
    __syncthreads();
    int idx = blockIdx.x * 8 + warp;
    if (idx < NP) layer3_proj_node<true >(idx,      d_pb, d_tb, d_rcnt, d_rlist, sWp, sBp, sWtA, d_pa, d_prt, sX[warp], lane);
    else          layer3_proj_node<false>(idx - NP, d_tb, d_pb, d_ccnt, d_clist, sWt, sBt, sWpA, d_ta, d_prp, sX[warp], lane);
}

// ---------------- L4 combine: contrib = relu(self64@Wself + agg(proj16) + B) . wac ----------------
__device__ __forceinline__ float l4_node(
    int node, const float* __restrict__ self_f, const float* __restrict__ proj_other,
    const int* __restrict__ cnt, const int* __restrict__ list,
    const float* sWself, const float* sB, const float* sWac,
    float* xs, int lane, int& n_out, const int*& lst_out)
{
#pragma unroll
    for (int k = lane; k < 64; k += 32) xs[k] = self_f[node * 64 + k];

    int v = lane & 3, g = lane >> 2;
    float4 acc = make_float4(0.f, 0.f, 0.f, 0.f);
    int n = min(cnt[node], CAP);
    const int* lst = list + node * CAP;
    n_out = n; lst_out = lst;
    for (int e = g; e < n; e += 8) {
        float4 t4 = *reinterpret_cast<const float4*>(proj_other + lst[e] * 16 + v * 4);
        acc.x += t4.x; acc.y += t4.y; acc.z += t4.z; acc.w += t4.w;
    }
#pragma unroll
    for (int d = 4; d > 0; d >>= 1) {
        acc.x += __shfl_down_sync(0xffffffffu, acc.x, d * 4);
        acc.y += __shfl_down_sync(0xffffffffu, acc.y, d * 4);
        acc.z += __shfl_down_sync(0xffffffffu, acc.z, d * 4);
        acc.w += __shfl_down_sync(0xffffffffu, acc.w, d * 4);
    }
    if (g == 0) *reinterpret_cast<float4*>(xs + 64 + v * 4) = acc;
    __syncwarp();

    float contrib = 0.f;
    if (lane < 16) {
        float a = sB[lane] + xs[64 + lane];
#pragma unroll
        for (int k = 0; k < 64; k++) a += xs[k] * sWself[k * 16 + lane];
        contrib = fmaxf(a, 0.f) * sWac[lane];
    }
#pragma unroll
    for (int d = 16; d > 0; d >>= 1)
        contrib += __shfl_down_sync(0xffffffffu, contrib, d);
    return contrib;   // lane 0
}

__global__ void __launch_bounds__(256) l4p_k(
    const float* __restrict__ wp4, const float* __restrict__ bp4,
    const float* __restrict__ wac)
{
    __shared__ float sW[1024], sB[16], sAC[16];
    __shared__ __align__(16) float sX[8][80];
    int tid = threadIdx.x, warp = tid >> 5, lane = tid & 31;
    for (int i = tid; i < 1024; i += 256) sW[i] = wp4[i];
    if (tid < 16) { sB[tid] = bp4[tid]; sAC[tid] = wac[tid]; }
    __syncthreads();
    int node = blockIdx.x * 8 + warp;
    int n; const int* lst;
    float c = l4_node(node, d_pa, d_prp, d_rcnt, d_rlist, sW, sB, sAC, sX[warp], lane, n, lst);
    if (lane == 0) d_lp[node] = c;
}

__global__ void __launch_bounds__(256) l4t_logits_k(
    const float* __restrict__ wt4, const float* __restrict__ bt4,
    const float* __restrict__ wac, const float* __restrict__ bac)
{
    __shared__ float sW[1024], sB[16], sAC[16];
    __shared__ __align__(16) float sX[8][80];
    int tid = threadIdx.x, warp = tid >> 5, lane = tid & 31;
    for (int i = tid; i < 1024; i += 256) sW[i] = wt4[1024 + i];   // self part (rows 64..127)
    if (tid < 16) { sB[tid] = bt4[tid]; sAC[tid] = wac[16 + tid]; }
    __syncthreads();
    int node = blockIdx.x * 8 + warp;
    int n; const int* lst;
    float c = l4_node(node, d_ta, d_prt, d_ccnt, d_clist, sW, sB, sAC, sX[warp], lane, n, lst);
    // gather scalar p-contributions over incident places
    float s = 0.f;
    for (int e = lane; e < n; e += 32) s += d_lp[lst[e]];
#pragma unroll
    for (int d = 16; d > 0; d >>= 1) s += __shfl_down_sync(0xffffffffu, s, d);
    if (lane == 0) d_logits[node] = s + c + bac[0];
}

// ---------------- softmax + ccnt reset ----------------
__global__ void __launch_bounds__(1024) softmax_k(float* __restrict__ out) {
    __shared__ float sm[1024];
    int tid = threadIdx.x;
    float m = -1e30f;
    for (int i = tid; i < NT; i += 1024) m = fmaxf(m, d_logits[i]);
    sm[tid] = m; __syncthreads();
    for (int s = 512; s > 0; s >>= 1) {
        if (tid < s) sm[tid] = fmaxf(sm[tid], sm[tid + s]);
        __syncthreads();
    }
    float mx = sm[0];
    __syncthreads();
    float s = 0.f;
    for (int i = tid; i < NT; i += 1024) s += __expf(d_logits[i] - mx);
    sm[tid] = s; __syncthreads();
    for (int st = 512; st > 0; st >>= 1) {
        if (tid < st) sm[tid] += sm[tid + st];
        __syncthreads();
    }
    float inv = 1.f / sm[0];
    for (int i = tid; i < NT; i += 1024) {
        out[i] = __expf(d_logits[i] - mx) * inv;
        d_ccnt[i] = 0;                    // reset for next launch
    }
}

// ---------------- launch ----------------
extern "C" void kernel_launch(void* const* d_in, const int* in_sizes, int n_in,
                              void* d_out, int out_size) {
    const float* p    = (const float*)d_in[0];
    const float* t    = (const float*)d_in[1];
    const float* adj  = (const float*)d_in[2];
    const float* w_p1 = (const float*)d_in[3];  const float* b_p1 = (const float*)d_in[4];
    const float* w_t1 = (const float*)d_in[5];  const float* b_t1 = (const float*)d_in[6];
    const float* w_p2 = (const float*)d_in[7];  const float* b_p2 = (const float*)d_in[8];
    const float* w_t2 = (const float*)d_in[9];  const float* b_t2 = (const float*)d_in[10];
    const float* w_p3 = (const float*)d_in[11]; const float* b_p3 = (const float*)d_in[12];
    const float* w_t3 = (const float*)d_in[13]; const float* b_t3 = (const float*)d_in[14];
    const float* w_p4 = (const float*)d_in[15]; const float* b_p4 = (const float*)d_in[16];
    const float* w_t4 = (const float*)d_in[17]; const float* b_t4 = (const float*)d_in[18];
    const float* w_ac = (const float*)d_in[19]; const float* b_ac = (const float*)d_in[20];
    float* out = (float*)d_out;

    build_k<<<NP, 256>>>(adj);
    l1_k<<<(NP + NT) / 8, 256>>>(p, t, w_p1, b_p1, w_t1, b_t1);
    l2_k<<<(NP + NT) / 8, 256>>>(w_p2, b_p2, w_t2, b_t2);
    l3_k<<<(NP + NT) / 8, 256>>>(w_p3, b_p3, w_t3, b_t3, w_p4, w_t4);
    l4p_k<<<NP / 8, 256>>>(w_p4, b_p4, w_ac);
    l4t_logits_k<<<NT / 8, 256>>>(w_t4, b_t4, w_ac, b_ac);
    softmax_k<<<1, 1024>>>(out);
}

// round 8
// speedup vs baseline: 1.3252x; 1.0362x over previous
#include <cuda_runtime.h>

#define NP 8192
#define NT 8192
#define CAP 256
#define ROW_F4 (NT/4)
#define NBH 592            // blocks per side for layer kernels

// ---------------- static scratch ----------------
__device__ __align__(16) float d_pa[NP * 64];
__device__ __align__(16) float d_pb[NP * 64];
__device__ __align__(16) float d_ta[NT * 64];
__device__ __align__(16) float d_tb[NT * 64];
__device__ __align__(16) float d_prp[NT * 16];   // t3 @ wp4_agg (for p-side L4)
__device__ __align__(16) float d_prt[NP * 16];   // p3 @ wt4_agg (for t-side L4)
__device__ float d_lp[NP];
__device__ float d_logits[NT];
__device__ int d_rcnt[NP];
__device__ int d_ccnt[NT];      // zero-init; re-zeroed by softmax kernel each launch
__device__ int d_rlist[NP * CAP];
__device__ int d_clist[NT * CAP];

// ---------------- build: block per row, 8 in-flight float4 loads per thread ----------------
__global__ void __launch_bounds__(256) build_k(const float* __restrict__ adj) {
    __shared__ int s_cnt;
    int row = blockIdx.x;
    if (threadIdx.x == 0) s_cnt = 0;
    __syncthreads();

    const float4* a4 = reinterpret_cast<const float4*>(adj) + (size_t)row * ROW_F4 + threadIdx.x;
    float4 v[8];
#pragma unroll
    for (int k = 0; k < 8; k++) v[k] = __ldcs(a4 + k * 256);

#pragma unroll
    for (int k = 0; k < 8; k++) {
        if (v[k].x != 0.f || v[k].y != 0.f || v[k].z != 0.f || v[k].w != 0.f) {
            int jb = (threadIdx.x + k * 256) << 2;
            float vals[4] = {v[k].x, v[k].y, v[k].z, v[k].w};
#pragma unroll
            for (int q = 0; q < 4; q++) {
                if (vals[q] != 0.f) {
                    int j = jb + q;
                    int slot = atomicAdd(&s_cnt, 1);
                    if (slot < CAP) d_rlist[row * CAP + slot] = j;
                    int cs = atomicAdd(&d_ccnt[j], 1);
                    if (cs < CAP) d_clist[j * CAP + cs] = row;
                }
            }
        }
    }
    __syncthreads();
    if (threadIdx.x == 0) d_rcnt[row] = min(s_cnt, CAP);
}

// ---------------- generic layer node ----------------
template <int IN, int OUT, bool SELF_FIRST>
__device__ __forceinline__ void layer_node(
    int node, const float* __restrict__ self_f, const float* __restrict__ other_f,
    const int* __restrict__ cnt, const int* __restrict__ list,
    const float* sW, const float* sB, float* __restrict__ out_f,
    float* xs, int lane)
{
    constexpr int C = 2 * IN;
    constexpr int SOFF = SELF_FIRST ? 0 : IN;
    constexpr int AOFF = SELF_FIRST ? IN : 0;
#pragma unroll
    for (int k = lane; k < IN; k += 32) xs[SOFF + k] = self_f[node * IN + k];

    constexpr int V = IN / 4;
    constexpr int G = 32 / V;
    int v = lane % V, g = lane / V;
    float4 acc = make_float4(0.f, 0.f, 0.f, 0.f);
    int n = min(cnt[node], CAP);
    const int* lst = list + node * CAP;
    for (int e = g; e < n; e += G) {
        float4 t4 = *reinterpret_cast<const float4*>(other_f + lst[e] * IN + v * 4);
        acc.x += t4.x; acc.y += t4.y; acc.z += t4.z; acc.w += t4.w;
    }
#pragma unroll
    for (int d = G / 2; d > 0; d >>= 1) {
        acc.x += __shfl_down_sync(0xffffffffu, acc.x, d * V);
        acc.y += __shfl_down_sync(0xffffffffu, acc.y, d * V);
        acc.z += __shfl_down_sync(0xffffffffu, acc.z, d * V);
        acc.w += __shfl_down_sync(0xffffffffu, acc.w, d * V);
    }
    if (g == 0) *reinterpret_cast<float4*>(xs + AOFF + v * 4) = acc;
    __syncwarp();

    constexpr int JPL = (OUT + 31) / 32;
    if (lane < OUT) {
        float a[JPL];
#pragma unroll
        for (int jj = 0; jj < JPL; jj++) a[jj] = sB[lane + jj * 32];
#pragma unroll
        for (int k = 0; k < C; k++) {
            float xv = xs[k];
#pragma unroll
            for (int jj = 0; jj < JPL; jj++) a[jj] += xv * sW[k * OUT + lane + jj * 32];
        }
#pragma unroll
        for (int jj = 0; jj < JPL; jj++)
            out_f[node * OUT + lane + jj * 32] = fmaxf(a[jj], 0.f);
    }
    __syncwarp();
}

// ---------------- L1: side-split, grid-stride ----------------
__global__ void __launch_bounds__(256) l1_k(
    const float* __restrict__ p0, const float* __restrict__ t0,
    const float* __restrict__ wp, const float* __restrict__ bp,
    const float* __restrict__ wt, const float* __restrict__ bt)
{
    __shared__ float sW[128], sB[8];
    __shared__ __align__(16) float sX[8][16];
    int tid = threadIdx.x, warp = tid >> 5, lane = tid & 31;
    int half = gridDim.x >> 1;
    bool pside = blockIdx.x < half;
    const float* W = pside ? wp : wt;
    const float* B = pside ? bp : bt;
    if (tid < 32) ((float4*)sW)[tid] = ((const float4*)W)[tid];
    if (tid < 8) sB[tid] = B[tid];
    __syncthreads();
    int bid = pside ? blockIdx.x : blockIdx.x - half;
    int stride = half * 8;
    if (pside) {
        for (int node = bid * 8 + warp; node < NP; node += stride)
            layer_node<8, 8, true >(node, p0, t0, d_rcnt, d_rlist, sW, sB, d_pa, sX[warp], lane);
    } else {
        for (int node = bid * 8 + warp; node < NT; node += stride)
            layer_node<8, 8, false>(node, t0, p0, d_ccnt, d_clist, sW, sB, d_ta, sX[warp], lane);
    }
}

// ---------------- L2: side-split, grid-stride ----------------
__global__ void __launch_bounds__(256) l2_k(
    const float* __restrict__ wp, const float* __restrict__ bp,
    const float* __restrict__ wt, const float* __restrict__ bt)
{
    __shared__ float sW[256], sB[16];
    __shared__ __align__(16) float sX[8][16];
    int tid = threadIdx.x, warp = tid >> 5, lane = tid & 31;
    int half = gridDim.x >> 1;
    bool pside = blockIdx.x < half;
    const float* W = pside ? wp : wt;
    const float* B = pside ? bp : bt;
    if (tid < 64) ((float4*)sW)[tid] = ((const float4*)W)[tid];
    if (tid < 16) sB[tid] = B[tid];
    __syncthreads();
    int bid = pside ? blockIdx.x : blockIdx.x - half;
    int stride = half * 8;
    if (pside) {
        for (int node = bid * 8 + warp; node < NP; node += stride)
            layer_node<8, 16, true >(node, d_pa, d_ta, d_rcnt, d_rlist, sW, sB, d_pb, sX[warp], lane);
    } else {
        for (int node = bid * 8 + warp; node < NT; node += stride)
            layer_node<8, 16, false>(node, d_ta, d_pa, d_ccnt, d_clist, sW, sB, d_tb, sX[warp], lane);
    }
}

// ---------------- L3 node + fused 64->16 projection ----------------
template <bool SELF_FIRST>
__device__ __forceinline__ void layer3_proj_node(
    int node, const float* __restrict__ self_f, const float* __restrict__ other_f,
    const int* __restrict__ cnt, const int* __restrict__ list,
    const float* sW, const float* sB, const float* sWagg,
    float* __restrict__ out_f, float* __restrict__ proj_f,
    float* xs, int lane)
{
    constexpr int IN = 16, OUT = 64;
    constexpr int SOFF = SELF_FIRST ? 0 : IN;
    constexpr int AOFF = SELF_FIRST ? IN : 0;
#pragma unroll
    for (int k = lane; k < IN; k += 32) xs[SOFF + k] = self_f[node * IN + k];

    int v = lane & 3, g = lane >> 2;
    float4 acc = make_float4(0.f, 0.f, 0.f, 0.f);
    int n = min(cnt[node], CAP);
    const int* lst = list + node * CAP;
    for (int e = g; e < n; e += 8) {
        float4 t4 = *reinterpret_cast<const float4*>(other_f + lst[e] * IN + v * 4);
        acc.x += t4.x; acc.y += t4.y; acc.z += t4.z; acc.w += t4.w;
    }
#pragma unroll
    for (int d = 4; d > 0; d >>= 1) {
        acc.x += __shfl_down_sync(0xffffffffu, acc.x, d * 4);
        acc.y += __shfl_down_sync(0xffffffffu, acc.y, d * 4);
        acc.z += __shfl_down_sync(0xffffffffu, acc.z, d * 4);
        acc.w += __shfl_down_sync(0xffffffffu, acc.w, d * 4);
    }
    if (g == 0) *reinterpret_cast<float4*>(xs + AOFF + v * 4) = acc;
    __syncwarp();

    float a0 = sB[lane], a1 = sB[lane + 32];
#pragma unroll
    for (int k = 0; k < 32; k++) {
        float xv = xs[k];
        a0 += xv * sW[k * OUT + lane];
        a1 += xv * sW[k * OUT + lane + 32];
    }
    a0 = fmaxf(a0, 0.f); a1 = fmaxf(a1, 0.f);
    out_f[node * OUT + lane] = a0;
    out_f[node * OUT + lane + 32] = a1;
    xs[lane] = a0; xs[lane + 32] = a1;
    __syncwarp();

    if (lane < 16) {
        float pr = 0.f;
#pragma unroll
        for (int k = 0; k < 64; k++) pr += xs[k] * sWagg[k * 16 + lane];
        proj_f[node * 16 + lane] = pr;
    }
    __syncwarp();
}

// ---------------- L3: side-split, grid-stride, f4 weight loads ----------------
__global__ void __launch_bounds__(256) l3_k(
    const float* __restrict__ wp3, const float* __restrict__ bp3,
    const float* __restrict__ wt3, const float* __restrict__ bt3,
    const float* __restrict__ wp4, const float* __restrict__ wt4)
{
    __shared__ float sW[2048], sWA[1024], sB[64];
    __shared__ __align__(16) float sX[8][128];
    int tid = threadIdx.x, warp = tid >> 5, lane = tid & 31;
    int half = gridDim.x >> 1;
    bool pside = blockIdx.x < half;
    const float* W  = pside ? wp3 : wt3;
    const float* B  = pside ? bp3 : bt3;
    const float* WA = pside ? wt4 : (wp4 + 1024);   // agg part used to project THIS side's output
    ((float4*)sW)[tid]        = ((const float4*)W)[tid];
    ((float4*)sW)[tid + 256]  = ((const float4*)W)[tid + 256];
    ((float4*)sWA)[tid]       = ((const float4*)WA)[tid];
    if (tid < 64) sB[tid] = B[tid];
    __syncthreads();
    int bid = pside ? blockIdx.x : blockIdx.x - half;
    int stride = half * 8;
    if (pside) {
        for (int node = bid * 8 + warp; node < NP; node += stride)
            layer3_proj_node<true >(node, d_pb, d_tb, d_rcnt, d_rlist, sW, sB, sWA, d_pa, d_prt, sX[warp], lane);
    } else {
        for (int node = bid * 8 + warp; node < NT; node += stride)
            layer3_proj_node<false>(node, d_tb, d_pb, d_ccnt, d_clist, sW, sB, sWA, d_ta, d_prp, sX[warp], lane);
    }
}

// ---------------- L4 combine node ----------------
__device__ __forceinline__ float l4_node(
    int node, const float* __restrict__ self_f, const float* __restrict__ proj_other,
    const int* __restrict__ cnt, const int* __restrict__ list,
    const float* sWself, const float* sB, const float* sAC,
    float* xs, int lane, int& n_out, const int*& lst_out)
{
#pragma unroll
    for (int k = lane; k < 64; k += 32) xs[k] = self_f[node * 64 + k];

    int v = lane & 3, g = lane >> 2;
    float4 acc = make_float4(0.f, 0.f, 0.f, 0.f);
    int n = min(cnt[node], CAP);
    const int* lst = list + node * CAP;
    n_out = n; lst_out = lst;
    for (int e = g; e < n; e += 8) {
        float4 t4 = *reinterpret_cast<const float4*>(proj_other + lst[e] * 16 + v * 4);
        acc.x += t4.x; acc.y += t4.y; acc.z += t4.z; acc.w += t4.w;
    }
#pragma unroll
    for (int d = 4; d > 0; d >>= 1) {
        acc.x += __shfl_down_sync(0xffffffffu, acc.x, d * 4);
        acc.y += __shfl_down_sync(0xffffffffu, acc.y, d * 4);
        acc.z += __shfl_down_sync(0xffffffffu, acc.z, d * 4);
        acc.w += __shfl_down_sync(0xffffffffu, acc.w, d * 4);
    }
    if (g == 0) *reinterpret_cast<float4*>(xs + 64 + v * 4) = acc;
    __syncwarp();

    float contrib = 0.f;
    if (lane < 16) {
        float a = sB[lane] + xs[64 + lane];
#pragma unroll
        for (int k = 0; k < 64; k++) a += xs[k] * sWself[k * 16 + lane];
        contrib = fmaxf(a, 0.f) * sAC[lane];
    }
#pragma unroll
    for (int d = 16; d > 0; d >>= 1)
        contrib += __shfl_down_sync(0xffffffffu, contrib, d);
    __syncwarp();
    return contrib;   // lane 0
}

// ---------------- L4 p-side ----------------
__global__ void __launch_bounds__(256) l4p_k(
    const float* __restrict__ wp4, const float* __restrict__ bp4,
    const float* __restrict__ wac)
{
    __shared__ float sW[1024], sB[16], sAC[16];
    __shared__ __align__(16) float sX[8][80];
    int tid = threadIdx.x, warp = tid >> 5, lane = tid & 31;
    ((float4*)sW)[tid] = ((const float4*)wp4)[tid];
    if (tid < 16) { sB[tid] = bp4[tid]; sAC[tid] = wac[tid]; }
    __syncthreads();
    int stride = gridDim.x * 8;
    for (int node = blockIdx.x * 8 + warp; node < NP; node += stride) {
        int n; const int* lst;
        float c = l4_node(node, d_pa, d_prp, d_rcnt, d_rlist, sW, sB, sAC, sX[warp], lane, n, lst);
        if (lane == 0) d_lp[node] = c;
    }
}

// ---------------- L4 t-side + logits ----------------
__global__ void __launch_bounds__(256) l4t_logits_k(
    const float* __restrict__ wt4, const float* __restrict__ bt4,
    const float* __restrict__ wac, const float* __restrict__ bac)
{
    __shared__ float sW[1024], sB[16], sAC[16];
    __shared__ __align__(16) float sX[8][80];
    int tid = threadIdx.x, warp = tid >> 5, lane = tid & 31;
    ((float4*)sW)[tid] = ((const float4*)(wt4 + 1024))[tid];   // self part (rows 64..127)
    if (tid < 16) { sB[tid] = bt4[tid]; sAC[tid] = wac[16 + tid]; }
    __syncthreads();
    float bias = bac[0];
    int stride = gridDim.x * 8;
    for (int node = blockIdx.x * 8 + warp; node < NT; node += stride) {
        int n; const int* lst;
        float c = l4_node(node, d_ta, d_prt, d_ccnt, d_clist, sW, sB, sAC, sX[warp], lane, n, lst);
        float s = 0.f;
        for (int e = lane; e < n; e += 32) s += d_lp[lst[e]];
#pragma unroll
        for (int d = 16; d > 0; d >>= 1) s += __shfl_down_sync(0xffffffffu, s, d);
        if (lane == 0) d_logits[node] = s + c + bias;
    }
}

// ---------------- softmax + ccnt reset ----------------
__global__ void __launch_bounds__(1024) softmax_k(float* __restrict__ out) {
    __shared__ float sm[1024];
    int tid = threadIdx.x;
    float m = -1e30f;
    for (int i = tid; i < NT; i += 1024) m = fmaxf(m, d_logits[i]);
    sm[tid] = m; __syncthreads();
    for (int s = 512; s > 0; s >>= 1) {
        if (tid < s) sm[tid] = fmaxf(sm[tid], sm[tid + s]);
        __syncthreads();
    }
    float mx = sm[0];
    __syncthreads();
    float s = 0.f;
    for (int i = tid; i < NT; i += 1024) s += __expf(d_logits[i] - mx);
    sm[tid] = s; __syncthreads();
    for (int st = 512; st > 0; st >>= 1) {
        if (tid < st) sm[tid] += sm[tid + st];
        __syncthreads();
    }
    float inv = 1.f / sm[0];
    for (int i = tid; i < NT; i += 1024) {
        out[i] = __expf(d_logits[i] - mx) * inv;
        d_ccnt[i] = 0;                    // reset for next launch
    }
}

// ---------------- launch ----------------
extern "C" void kernel_launch(void* const* d_in, const int* in_sizes, int n_in,
                              void* d_out, int out_size) {
    const float* p    = (const float*)d_in[0];
    const float* t    = (const float*)d_in[1];
    const float* adj  = (const float*)d_in[2];
    const float* w_p1 = (const float*)d_in[3];  const float* b_p1 = (const float*)d_in[4];
    const float* w_t1 = (const float*)d_in[5];  const float* b_t1 = (const float*)d_in[6];
    const float* w_p2 = (const float*)d_in[7];  const float* b_p2 = (const float*)d_in[8];
    const float* w_t2 = (const float*)d_in[9];  const float* b_t2 = (const float*)d_in[10];
    const float* w_p3 = (const float*)d_in[11]; const float* b_p3 = (const float*)d_in[12];
    const float* w_t3 = (const float*)d_in[13]; const float* b_t3 = (const float*)d_in[14];
    const float* w_p4 = (const float*)d_in[15]; const float* b_p4 = (const float*)d_in[16];
    const float* w_t4 = (const float*)d_in[17]; const float* b_t4 = (const float*)d_in[18];
    const float* w_ac = (const float*)d_in[19]; const float* b_ac = (const float*)d_in[20];
    float* out = (float*)d_out;

    build_k<<<NP, 256>>>(adj);
    l1_k<<<2 * NBH, 256>>>(p, t, w_p1, b_p1, w_t1, b_t1);
    l2_k<<<2 * NBH, 256>>>(w_p2, b_p2, w_t2, b_t2);
    l3_k<<<2 * NBH, 256>>>(w_p3, b_p3, w_t3, b_t3, w_p4, w_t4);
    l4p_k<<<NBH, 256>>>(w_p4, b_p4, w_ac);
    l4t_logits_k<<<NBH, 256>>>(w_t4, b_t4, w_ac, b_ac);
    softmax_k<<<1, 1024>>>(out);
}

// round 10
// speedup vs baseline: 1.3282x; 1.0023x over previous
#include <cuda_runtime.h>

#define NP 8192
#define NT 8192
#define CAP 256
#define ROW_F4 (NT/4)
#define NBH 592            // blocks per side for layer kernels
#define FULLM 0xffffffffu

// ---------------- static scratch ----------------
__device__ __align__(16) float d_pa[NP * 64];
__device__ __align__(16) float d_pb[NP * 64];
__device__ __align__(16) float d_ta[NT * 64];
__device__ __align__(16) float d_tb[NT * 64];
__device__ __align__(16) float d_prp[NT * 16];   // t3 @ wp4_agg (for p-side L4)
__device__ __align__(16) float d_prt[NP * 16];   // p3 @ wt4_agg (for t-side L4)
__device__ float d_lp[NP];
__device__ float d_logits[NT];
__device__ int d_rcnt[NP];
__device__ int d_ccnt[NT];      // zero-init; re-zeroed by softmax kernel each launch
__device__ int d_rlist[NP * CAP];
__device__ int d_clist[NT * CAP];

// ---------------- build: block per row, 8 in-flight float4 loads per thread ----------------
__global__ void __launch_bounds__(256) build_k(const float* __restrict__ adj) {
    __shared__ int s_cnt;
    int row = blockIdx.x;
    if (threadIdx.x == 0) s_cnt = 0;
    __syncthreads();

    const float4* a4 = reinterpret_cast<const float4*>(adj) + (size_t)row * ROW_F4 + threadIdx.x;
    float4 v[8];
#pragma unroll
    for (int k = 0; k < 8; k++) v[k] = __ldcs(a4 + k * 256);

#pragma unroll
    for (int k = 0; k < 8; k++) {
        if (v[k].x != 0.f || v[k].y != 0.f || v[k].z != 0.f || v[k].w != 0.f) {
            int jb = (threadIdx.x + k * 256) << 2;
            float vals[4] = {v[k].x, v[k].y, v[k].z, v[k].w};
#pragma unroll
            for (int q = 0; q < 4; q++) {
                if (vals[q] != 0.f) {
                    int j = jb + q;
                    int slot = atomicAdd(&s_cnt, 1);
                    if (slot < CAP) d_rlist[row * CAP + slot] = j;
                    int cs = atomicAdd(&d_ccnt[j], 1);
                    if (cs < CAP) d_clist[j * CAP + cs] = row;
                }
            }
        }
    }
    __syncthreads();
    if (threadIdx.x == 0) d_rcnt[row] = min(s_cnt, CAP);
}

// ---------------- shfl-based neighbor index fetch (e < 64) ----------------
__device__ __forceinline__ int shfl_idx(int e, int i0, int i1) {
    int v = (e & 32) ? i1 : i0;
    return __shfl_sync(FULLM, v, e & 31);
}

// ---------------- gather sum of float4 slices over neighbor list ----------------
// Returns partial sums; lanes with g==0 hold the final slice sums after reduction.
// i0/i1 are returned so callers can reuse the coalesced index registers.
template <int IN>
__device__ __forceinline__ float4 gather_agg(
    const float* __restrict__ feat, const int* __restrict__ lst, int n,
    int lane, int& i0, int& i1)
{
    constexpr int V = IN / 4;
    constexpr int G = 32 / V;
    int v = lane % V, g = lane / V;
    i0 = (lane < n) ? lst[lane] : 0;
    i1 = (lane + 32 < n) ? lst[lane + 32] : 0;
    int nlim = min(n, 64);
    int iters = (nlim + G - 1) / G;        // warp-uniform
    float4 a0 = make_float4(0.f, 0.f, 0.f, 0.f);
    float4 a1 = make_float4(0.f, 0.f, 0.f, 0.f);
    int k = 0;
    for (; k + 1 < iters; k += 2) {
        int e0 = g + k * G, e1 = e0 + G;
        int n0 = shfl_idx(e0, i0, i1);
        int n1 = shfl_idx(e1, i0, i1);
        float4 t0 = *reinterpret_cast<const float4*>(feat + n0 * IN + v * 4);
        a0.x += t0.x; a0.y += t0.y; a0.z += t0.z; a0.w += t0.w;
        if (e1 < nlim) {
            float4 t1 = *reinterpret_cast<const float4*>(feat + n1 * IN + v * 4);
            a1.x += t1.x; a1.y += t1.y; a1.z += t1.z; a1.w += t1.w;
        }
    }
    if (k < iters) {
        int e0 = g + k * G;
        int n0 = shfl_idx(e0, i0, i1);
        if (e0 < nlim) {
            float4 t0 = *reinterpret_cast<const float4*>(feat + n0 * IN + v * 4);
            a0.x += t0.x; a0.y += t0.y; a0.z += t0.z; a0.w += t0.w;
        }
    }
    if (n > 64) {                           // rare tail, warp-uniform loop
        for (int e = 64 + g; __any_sync(FULLM, e < n); e += G) {
            if (e < n) {
                int nb = lst[e];
                float4 t = *reinterpret_cast<const float4*>(feat + nb * IN + v * 4);
                a0.x += t.x; a0.y += t.y; a0.z += t.z; a0.w += t.w;
            }
        }
    }
    a0.x += a1.x; a0.y += a1.y; a0.z += a1.z; a0.w += a1.w;
#pragma unroll
    for (int d = G / 2; d > 0; d >>= 1) {
        a0.x += __shfl_down_sync(FULLM, a0.x, d * V);
        a0.y += __shfl_down_sync(FULLM, a0.y, d * V);
        a0.z += __shfl_down_sync(FULLM, a0.z, d * V);
        a0.w += __shfl_down_sync(FULLM, a0.w, d * V);
    }
    return a0;
}

// ---------------- generic layer node ----------------
template <int IN, int OUT, bool SELF_FIRST>
__device__ __forceinline__ void layer_node(
    int node, const float* __restrict__ self_f, const float* __restrict__ other_f,
    const int* __restrict__ cnt, const int* __restrict__ list,
    const float* sW, const float* sB, float* __restrict__ out_f,
    float* xs, int lane)
{
    constexpr int C = 2 * IN;
    constexpr int SOFF = SELF_FIRST ? 0 : IN;
    constexpr int AOFF = SELF_FIRST ? IN : 0;
#pragma unroll
    for (int k = lane; k < IN; k += 32) xs[SOFF + k] = self_f[node * IN + k];

    int n = min(cnt[node], CAP);
    const int* lst = list + node * CAP;
    int i0, i1;
    float4 acc = gather_agg<IN>(other_f, lst, n, lane, i0, i1);
    constexpr int V = IN / 4;
    int v = lane % V, g = lane / V;
    if (g == 0) *reinterpret_cast<float4*>(xs + AOFF + v * 4) = acc;
    __syncwarp();

    constexpr int JPL = (OUT + 31) / 32;
    if (lane < OUT) {
        float a[JPL];
#pragma unroll
        for (int jj = 0; jj < JPL; jj++) a[jj] = sB[lane + jj * 32];
#pragma unroll
        for (int k = 0; k < C; k++) {
            float xv = xs[k];
#pragma unroll
            for (int jj = 0; jj < JPL; jj++) a[jj] += xv * sW[k * OUT + lane + jj * 32];
        }
#pragma unroll
        for (int jj = 0; jj < JPL; jj++)
            out_f[node * OUT + lane + jj * 32] = fmaxf(a[jj], 0.f);
    }
    __syncwarp();
}

// ---------------- L1: side-split, grid-stride ----------------
__global__ void __launch_bounds__(256) l1_k(
    const float* __restrict__ p0, const float* __restrict__ t0,
    const float* __restrict__ wp, const float* __restrict__ bp,
    const float* __restrict__ wt, const float* __restrict__ bt)
{
    __shared__ float sW[128], sB[8];
    __shared__ __align__(16) float sX[8][16];
    int tid = threadIdx.x, warp = tid >> 5, lane = tid & 31;
    int half = gridDim.x >> 1;
    bool pside = blockIdx.x < half;
    const float* W = pside ? wp : wt;
    const float* B = pside ? bp : bt;
    if (tid < 32) ((float4*)sW)[tid] = ((const float4*)W)[tid];
    if (tid < 8) sB[tid] = B[tid];
    __syncthreads();
    int bid = pside ? blockIdx.x : blockIdx.x - half;
    int stride = half * 8;
    if (pside) {
        for (int node = bid * 8 + warp; node < NP; node += stride)
            layer_node<8, 8, true >(node, p0, t0, d_rcnt, d_rlist, sW, sB, d_pa, sX[warp], lane);
    } else {
        for (int node = bid * 8 + warp; node < NT; node += stride)
            layer_node<8, 8, false>(node, t0, p0, d_ccnt, d_clist, sW, sB, d_ta, sX[warp], lane);
    }
}

// ---------------- L2: side-split, grid-stride ----------------
__global__ void __launch_bounds__(256) l2_k(
    const float* __restrict__ wp, const float* __restrict__ bp,
    const float* __restrict__ wt, const float* __restrict__ bt)
{
    __shared__ float sW[256], sB[16];
    __shared__ __align__(16) float sX[8][16];
    int tid = threadIdx.x, warp = tid >> 5, lane = tid & 31;
    int half = gridDim.x >> 1;
    bool pside = blockIdx.x < half;
    const float* W = pside ? wp : wt;
    const float* B = pside ? bp : bt;
    if (tid < 64) ((float4*)sW)[tid] = ((const float4*)W)[tid];
    if (tid < 16) sB[tid] = B[tid];
    __syncthreads();
    int bid = pside ? blockIdx.x : blockIdx.x - half;
    int stride = half * 8;
    if (pside) {
        for (int node = bid * 8 + warp; node < NP; node += stride)
            layer_node<8, 16, true >(node, d_pa, d_ta, d_rcnt, d_rlist, sW, sB, d_pb, sX[warp], lane);
    } else {
        for (int node = bid * 8 + warp; node < NT; node += stride)
            layer_node<8, 16, false>(node, d_ta, d_pa, d_ccnt, d_clist, sW, sB, d_tb, sX[warp], lane);
    }
}

// ---------------- L3 node + fused 64->16 projection ----------------
template <bool SELF_FIRST>
__device__ __forceinline__ void layer3_proj_node(
    int node, const float* __restrict__ self_f, const float* __restrict__ other_f,
    const int* __restrict__ cnt, const int* __restrict__ list,
    const float* sW, const float* sB, const float* sWagg,
    float* __restrict__ out_f, float* __restrict__ proj_f,
    float* xs, int lane)
{
    constexpr int IN = 16, OUT = 64;
    constexpr int SOFF = SELF_FIRST ? 0 : IN;
    constexpr int AOFF = SELF_FIRST ? IN : 0;
#pragma unroll
    for (int k = lane; k < IN; k += 32) xs[SOFF + k] = self_f[node * IN + k];

    int n = min(cnt[node], CAP);
    const int* lst = list + node * CAP;
    int i0, i1;
    float4 acc = gather_agg<16>(other_f, lst, n, lane, i0, i1);
    int v = lane & 3, g = lane >> 2;
    if (g == 0) *reinterpret_cast<float4*>(xs + AOFF + v * 4) = acc;
    __syncwarp();

    float a0 = sB[lane], a1 = sB[lane + 32];
#pragma unroll
    for (int k = 0; k < 32; k++) {
        float xv = xs[k];
        a0 += xv * sW[k * OUT + lane];
        a1 += xv * sW[k * OUT + lane + 32];
    }
    a0 = fmaxf(a0, 0.f); a1 = fmaxf(a1, 0.f);
    out_f[node * OUT + lane] = a0;
    out_f[node * OUT + lane + 32] = a1;
    xs[lane] = a0; xs[lane + 32] = a1;
    __syncwarp();

    if (lane < 16) {
        float pr = 0.f;
#pragma unroll
        for (int k = 0; k < 64; k++) pr += xs[k] * sWagg[k * 16 + lane];
        proj_f[node * 16 + lane] = pr;
    }
    __syncwarp();
}

// ---------------- L3: side-split, grid-stride, f4 weight loads ----------------
__global__ void __launch_bounds__(256) l3_k(
    const float* __restrict__ wp3, const float* __restrict__ bp3,
    const float* __restrict__ wt3, const float* __restrict__ bt3,
    const float* __restrict__ wp4, const float* __restrict__ wt4)
{
    __shared__ float sW[2048], sWA[1024], sB[64];
    __shared__ __align__(16) float sX[8][128];
    int tid = threadIdx.x, warp = tid >> 5, lane = tid & 31;
    int half = gridDim.x >> 1;
    bool pside = blockIdx.x < half;
    const float* W  = pside ? wp3 : wt3;
    const float* B  = pside ? bp3 : bt3;
    const float* WA = pside ? wt4 : (wp4 + 1024);   // agg part projecting THIS side's output
    ((float4*)sW)[tid]        = ((const float4*)W)[tid];
    ((float4*)sW)[tid + 256]  = ((const float4*)W)[tid + 256];
    ((float4*)sWA)[tid]       = ((const float4*)WA)[tid];
    if (tid < 64) sB[tid] = B[tid];
    __syncthreads();
    int bid = pside ? blockIdx.x : blockIdx.x - half;
    int stride = half * 8;
    if (pside) {
        for (int node = bid * 8 + warp; node < NP; node += stride)
            layer3_proj_node<true >(node, d_pb, d_tb, d_rcnt, d_rlist, sW, sB, sWA, d_pa, d_prt, sX[warp], lane);
    } else {
        for (int node = bid * 8 + warp; node < NT; node += stride)
            layer3_proj_node<false>(node, d_tb, d_pb, d_ccnt, d_clist, sW, sB, sWA, d_ta, d_prp, sX[warp], lane);
    }
}

// ---------------- L4 combine node ----------------
__device__ __forceinline__ float l4_node(
    int node, const float* __restrict__ self_f, const float* __restrict__ proj_other,
    const int* __restrict__ cnt, const int* __restrict__ list,
    const float* sWself, const float* sB, const float* sAC,
    float* xs, int lane, int& n_out, int& i0, int& i1, const int*& lst_out)
{
#pragma unroll
    for (int k = lane; k < 64; k += 32) xs[k] = self_f[node * 64 + k];

    int n = min(cnt[node], CAP);
    const int* lst = list + node * CAP;
    n_out = n; lst_out = lst;
    float4 acc = gather_agg<16>(proj_other, lst, n, lane, i0, i1);
    int v = lane & 3, g = lane >> 2;
    if (g == 0) *reinterpret_cast<float4*>(xs + 64 + v * 4) = acc;
    __syncwarp();

    float contrib = 0.f;
    if (lane < 16) {
        float a = sB[lane] + xs[64 + lane];
#pragma unroll
        for (int k = 0; k < 64; k++) a += xs[k] * sWself[k * 16 + lane];
        contrib = fmaxf(a, 0.f) * sAC[lane];
    }
#pragma unroll
    for (int d = 16; d > 0; d >>= 1)
        contrib += __shfl_down_sync(FULLM, contrib, d);
    __syncwarp();
    return contrib;   // lane 0
}

// ---------------- L4 p-side ----------------
__global__ void __launch_bounds__(256) l4p_k(
    const float* __restrict__ wp4, const float* __restrict__ bp4,
    const float* __restrict__ wac)
{
    __shared__ float sW[1024], sB[16], sAC[16];
    __shared__ __align__(16) float sX[8][80];
    int tid = threadIdx.x, warp = tid >> 5, lane = tid & 31;
    ((float4*)sW)[tid] = ((const float4*)wp4)[tid];
    if (tid < 16) { sB[tid] = bp4[tid]; sAC[tid] = wac[tid]; }
    __syncthreads();
    int stride = gridDim.x * 8;
    for (int node = blockIdx.x * 8 + warp; node < NP; node += stride) {
        int n, i0, i1; const int* lst;
        float c = l4_node(node, d_pa, d_prp, d_rcnt, d_rlist, sW, sB, sAC, sX[warp], lane, n, i0, i1, lst);
        if (lane == 0) d_lp[node] = c;
    }
}

// ---------------- L4 t-side + logits ----------------
__global__ void __launch_bounds__(256) l4t_logits_k(
    const float* __restrict__ wt4, const float* __restrict__ bt4,
    const float* __restrict__ wac, const float* __restrict__ bac)
{
    __shared__ float sW[1024], sB[16], sAC[16];
    __shared__ __align__(16) float sX[8][80];
    int tid = threadIdx.x, warp = tid >> 5, lane = tid & 31;
    ((float4*)sW)[tid] = ((const float4*)(wt4 + 1024))[tid];   // self part (rows 64..127)
    if (tid < 16) { sB[tid] = bt4[tid]; sAC[tid] = wac[16 + tid]; }
    __syncthreads();
    float bias = bac[0];
    int stride = gridDim.x * 8;
    for (int node = blockIdx.x * 8 + warp; node < NT; node += stride) {
        int n, i0, i1; const int* lst;
        float c = l4_node(node, d_ta, d_prt, d_ccnt, d_clist, sW, sB, sAC, sX[warp], lane, n, i0, i1, lst);
        // scalar p-contribution gather — indices already in registers
        float s = 0.f;
        if (lane < n) s += d_lp[i0];
        if (lane + 32 < n) s += d_lp[i1];
        if (n > 64) {
            for (int e = 64 + lane; __any_sync(FULLM, e < n); e += 32)
                if (e < n) s += d_lp[lst[e]];
        }
#pragma unroll
        for (int d = 16; d > 0; d >>= 1) s += __shfl_down_sync(FULLM, s, d);
        if (lane == 0) d_logits[node] = s + c + bias;
    }
}

// ---------------- softmax + ccnt reset ----------------
__global__ void __launch_bounds__(1024) softmax_k(float* __restrict__ out) {
    __shared__ float sm[1024];
    int tid = threadIdx.x;
    float m = -1e30f;
    for (int i = tid; i < NT; i += 1024) m = fmaxf(m, d_logits[i]);
    sm[tid] = m; __syncthreads();
    for (int s = 512; s > 0; s >>= 1) {
        if (tid < s) sm[tid] = fmaxf(sm[tid], sm[tid + s]);
        __syncthreads();
    }
    float mx = sm[0];
    __syncthreads();
    float s = 0.f;
    for (int i = tid; i < NT; i += 1024) s += __expf(d_logits[i] - mx);
    sm[tid] = s; __syncthreads();
    for (int st = 512; st > 0; st >>= 1) {
        if (tid < st) sm[tid] += sm[tid + st];
        __syncthreads();
    }
    float inv = 1.f / sm[0];
    for (int i = tid; i < NT; i += 1024) {
        out[i] = __expf(d_logits[i] - mx) * inv;
        d_ccnt[i] = 0;                    // reset for next launch
    }
}

// ---------------- launch ----------------
extern "C" void kernel_launch(void* const* d_in, const int* in_sizes, int n_in,
                              void* d_out, int out_size) {
    const float* p    = (const float*)d_in[0];
    const float* t    = (const float*)d_in[1];
    const float* adj  = (const float*)d_in[2];
    const float* w_p1 = (const float*)d_in[3];  const float* b_p1 = (const float*)d_in[4];
    const float* w_t1 = (const float*)d_in[5];  const float* b_t1 = (const float*)d_in[6];
    const float* w_p2 = (const float*)d_in[7];  const float* b_p2 = (const float*)d_in[8];
    const float* w_t2 = (const float*)d_in[9];  const float* b_t2 = (const float*)d_in[10];
    const float* w_p3 = (const float*)d_in[11]; const float* b_p3 = (const float*)d_in[12];
    const float* w_t3 = (const float*)d_in[13]; const float* b_t3 = (const float*)d_in[14];
    const float* w_p4 = (const float*)d_in[15]; const float* b_p4 = (const float*)d_in[16];
    const float* w_t4 = (const float*)d_in[17]; const float* b_t4 = (const float*)d_in[18];
    const float* w_ac = (const float*)d_in[19]; const float* b_ac = (const float*)d_in[20];
    float* out = (float*)d_out;

    build_k<<<NP, 256>>>(adj);
    l1_k<<<2 * NBH, 256>>>(p, t, w_p1, b_p1, w_t1, b_t1);
    l2_k<<<2 * NBH, 256>>>(w_p2, b_p2, w_t2, b_t2);
    l3_k<<<2 * NBH, 256>>>(w_p3, b_p3, w_t3, b_t3, w_p4, w_t4);
    l4p_k<<<NBH, 256>>>(w_p4, b_p4, w_ac);
    l4t_logits_k<<<NBH, 256>>>(w_t4, b_t4, w_ac, b_ac);
    softmax_k<<<1, 1024>>>(out);
}

// round 12
// speedup vs baseline: 1.4013x; 1.0550x over previous
#include <cuda_runtime.h>

#define NP 8192
#define NT 8192
#define CAP 256
#define ROW_F4 (NT/4)
#define NBH 592
#define FULLM 0xffffffffu

// ---------------- static scratch ----------------
__device__ __align__(16) float d_pa[NP * 64];
__device__ __align__(16) float d_pb[NP * 64];
__device__ __align__(16) float d_ta[NT * 64];
__device__ __align__(16) float d_tb[NT * 64];
__device__ __align__(16) float d_prp[NT * 16];   // t3 @ wp4_agg (for p-side L4)
__device__ __align__(16) float d_prt[NP * 16];   // p3 @ wt4_agg (for t-side L4)
__device__ float d_lp[NP];
__device__ float d_logits[NT];
__device__ int d_rcnt[NP];
__device__ int d_ccnt[NT];      // zero-init; re-zeroed by softmax kernel each launch
__device__ int d_rlist[NP * CAP];
__device__ int d_clist[NT * CAP];

// index into padded C=64,OUT=16 weight layout (conflict-free two k-halves)
#define W64X16(k, c) ((k) * 17 + (((k) >> 5) << 4) + (c))
// index into padded C=64,OUT=16 projection layout (stride 16 + half rotation)
#define WA64X16(k, c) ((k) * 16 + (((k) >> 5) << 4) + (c))

// ---------------- build: block per row, 8 in-flight float4 loads per thread ----------------
__global__ void __launch_bounds__(256) build_k(const float* __restrict__ adj) {
    __shared__ int s_cnt;
    int row = blockIdx.x;
    if (threadIdx.x == 0) s_cnt = 0;
    __syncthreads();

    const float4* a4 = reinterpret_cast<const float4*>(adj) + (size_t)row * ROW_F4 + threadIdx.x;
    float4 v[8];
#pragma unroll
    for (int k = 0; k < 8; k++) v[k] = __ldcs(a4 + k * 256);

#pragma unroll
    for (int k = 0; k < 8; k++) {
        if (v[k].x != 0.f || v[k].y != 0.f || v[k].z != 0.f || v[k].w != 0.f) {
            int jb = (threadIdx.x + k * 256) << 2;
            float vals[4] = {v[k].x, v[k].y, v[k].z, v[k].w};
#pragma unroll
            for (int q = 0; q < 4; q++) {
                if (vals[q] != 0.f) {
                    int j = jb + q;
                    int slot = atomicAdd(&s_cnt, 1);
                    if (slot < CAP) d_rlist[row * CAP + slot] = j;
                    int cs = atomicAdd(&d_ccnt[j], 1);
                    if (cs < CAP) d_clist[j * CAP + cs] = row;
                }
            }
        }
    }
    __syncthreads();
    if (threadIdx.x == 0) d_rcnt[row] = min(s_cnt, CAP);
}

// ---------------- shfl-based neighbor index fetch (e < 64) ----------------
__device__ __forceinline__ int shfl_idx(int e, int i0, int i1) {
    int v = (e & 32) ? i1 : i0;
    return __shfl_sync(FULLM, v, e & 31);
}

// ---------------- gather sum of float4 slices over neighbor list ----------------
template <int IN>
__device__ __forceinline__ float4 gather_agg(
    const float* __restrict__ feat, const int* __restrict__ lst, int n,
    int lane, int& i0, int& i1)
{
    constexpr int V = IN / 4;
    constexpr int G = 32 / V;
    int v = lane % V, g = lane / V;
    i0 = (lane < n) ? lst[lane] : 0;
    i1 = (lane + 32 < n) ? lst[lane + 32] : 0;
    int nlim = min(n, 64);
    int iters = (nlim + G - 1) / G;        // warp-uniform
    float4 a0 = make_float4(0.f, 0.f, 0.f, 0.f);
    float4 a1 = make_float4(0.f, 0.f, 0.f, 0.f);
    int k = 0;
    for (; k + 1 < iters; k += 2) {
        int e0 = g + k * G, e1 = e0 + G;
        int n0 = shfl_idx(e0, i0, i1);
        int n1 = shfl_idx(e1, i0, i1);
        float4 t0 = *reinterpret_cast<const float4*>(feat + n0 * IN + v * 4);
        a0.x += t0.x; a0.y += t0.y; a0.z += t0.z; a0.w += t0.w;
        if (e1 < nlim) {
            float4 t1 = *reinterpret_cast<const float4*>(feat + n1 * IN + v * 4);
            a1.x += t1.x; a1.y += t1.y; a1.z += t1.z; a1.w += t1.w;
        }
    }
    if (k < iters) {
        int e0 = g + k * G;
        int n0 = shfl_idx(e0, i0, i1);
        if (e0 < nlim) {
            float4 t0 = *reinterpret_cast<const float4*>(feat + n0 * IN + v * 4);
            a0.x += t0.x; a0.y += t0.y; a0.z += t0.z; a0.w += t0.w;
        }
    }
    if (n > 64) {
        for (int e = 64 + g; __any_sync(FULLM, e < n); e += G) {
            if (e < n) {
                int nb = lst[e];
                float4 t = *reinterpret_cast<const float4*>(feat + nb * IN + v * 4);
                a0.x += t.x; a0.y += t.y; a0.z += t.z; a0.w += t.w;
            }
        }
    }
    a0.x += a1.x; a0.y += a1.y; a0.z += a1.z; a0.w += a1.w;
#pragma unroll
    for (int d = G / 2; d > 0; d >>= 1) {
        a0.x += __shfl_down_sync(FULLM, a0.x, d * V);
        a0.y += __shfl_down_sync(FULLM, a0.y, d * V);
        a0.z += __shfl_down_sync(FULLM, a0.z, d * V);
        a0.w += __shfl_down_sync(FULLM, a0.w, d * V);
    }
    return a0;
}

// ---------------- k-split column GEMM: all 32 lanes, padded weights (stride OUT+1) ----------------
// lanes = OUT cols x (32/OUT) k-groups; returns full dot for lanes < OUT (post shfl-combine).
template <int C, int OUT>
__device__ __forceinline__ float gemm_kcol(const float* xs, const float* sW, int lane) {
    constexpr int SPLIT = 32 / OUT;
    constexpr int KP = C / SPLIT;
    int col = lane & (OUT - 1);
    int grp = lane / OUT;
    int k0 = grp * KP;
    float acc = 0.f;
#pragma unroll
    for (int k = 0; k < KP; k += 4) {
        float4 xv = *reinterpret_cast<const float4*>(xs + k0 + k);
        acc += xv.x * sW[(k0 + k)     * (OUT + 2) + col];
        acc += xv.y * sW[(k0 + k + 1) * (OUT + 2) + col];
        acc += xv.z * sW[(k0 + k + 2) * (OUT + 2) + col];
        acc += xv.w * sW[(k0 + k + 3) * (OUT + 2) + col];
    }
#pragma unroll
    for (int d = OUT; d < 32; d <<= 1) acc += __shfl_down_sync(FULLM, acc, d);
    return acc;
}

// ---------------- generic layer node (OUT <= 32) ----------------
template <int IN, int OUT, bool SELF_FIRST>
__device__ __forceinline__ void layer_node(
    int node, const float* __restrict__ self_f, const float* __restrict__ other_f,
    const int* __restrict__ cnt, const int* __restrict__ list,
    const float* sW, const float* sB, float* __restrict__ out_f,
    float* xs, int lane)
{
    constexpr int C = 2 * IN;
    constexpr int SOFF = SELF_FIRST ? 0 : IN;
    constexpr int AOFF = SELF_FIRST ? IN : 0;
#pragma unroll
    for (int k = lane; k < IN; k += 32) xs[SOFF + k] = self_f[node * IN + k];

    int n = min(cnt[node], CAP);
    const int* lst = list + node * CAP;
    int i0, i1;
    float4 acc = gather_agg<IN>(other_f, lst, n, lane, i0, i1);
    constexpr int V = IN / 4;
    int v = lane % V, g = lane / V;
    if (g == 0) *reinterpret_cast<float4*>(xs + AOFF + v * 4) = acc;
    __syncwarp();

    float a = gemm_kcol<C, OUT>(xs, sW, lane);
    if (lane < OUT) out_f[node * OUT + lane] = fmaxf(a + sB[lane], 0.f);
    __syncwarp();
}

// ---------------- L1: side-split, grid-stride ----------------
__global__ void __launch_bounds__(256) l1_k(
    const float* __restrict__ p0, const float* __restrict__ t0,
    const float* __restrict__ wp, const float* __restrict__ bp,
    const float* __restrict__ wt, const float* __restrict__ bt)
{
    __shared__ float sW[16 * 10], sB[8];
    __shared__ __align__(16) float sX[8][16];
    int tid = threadIdx.x, warp = tid >> 5, lane = tid & 31;
    int half = gridDim.x >> 1;
    bool pside = blockIdx.x < half;
    const float* W = pside ? wp : wt;
    const float* B = pside ? bp : bt;
    if (tid < 128) sW[(tid >> 3) * 10 + (tid & 7)] = W[tid];
    if (tid < 8) sB[tid] = B[tid];
    __syncthreads();
    int bid = pside ? blockIdx.x : blockIdx.x - half;
    int stride = half * 8;
    if (pside) {
        for (int node = bid * 8 + warp; node < NP; node += stride)
            layer_node<8, 8, true >(node, p0, t0, d_rcnt, d_rlist, sW, sB, d_pa, sX[warp], lane);
    } else {
        for (int node = bid * 8 + warp; node < NT; node += stride)
            layer_node<8, 8, false>(node, t0, p0, d_ccnt, d_clist, sW, sB, d_ta, sX[warp], lane);
    }
}

// ---------------- L2: side-split, grid-stride ----------------
__global__ void __launch_bounds__(256) l2_k(
    const float* __restrict__ wp, const float* __restrict__ bp,
    const float* __restrict__ wt, const float* __restrict__ bt)
{
    __shared__ float sW[16 * 18], sB[16];
    __shared__ __align__(16) float sX[8][16];
    int tid = threadIdx.x, warp = tid >> 5, lane = tid & 31;
    int half = gridDim.x >> 1;
    bool pside = blockIdx.x < half;
    const float* W = pside ? wp : wt;
    const float* B = pside ? bp : bt;
    if (tid < 256) sW[(tid >> 4) * 18 + (tid & 15)] = W[tid];
    if (tid < 16) sB[tid] = B[tid];
    __syncthreads();
    int bid = pside ? blockIdx.x : blockIdx.x - half;
    int stride = half * 8;
    if (pside) {
        for (int node = bid * 8 + warp; node < NP; node += stride)
            layer_node<8, 16, true >(node, d_pa, d_ta, d_rcnt, d_rlist, sW, sB, d_pb, sX[warp], lane);
    } else {
        for (int node = bid * 8 + warp; node < NT; node += stride)
            layer_node<8, 16, false>(node, d_ta, d_pa, d_ccnt, d_clist, sW, sB, d_tb, sX[warp], lane);
    }
}

// ---------------- L3 node: float2-column GEMM + all-lane projection ----------------
template <bool SELF_FIRST>
__device__ __forceinline__ void layer3_proj_node(
    int node, const float* __restrict__ self_f, const float* __restrict__ other_f,
    const int* __restrict__ cnt, const int* __restrict__ list,
    const float* sW, const float* sB, const float* sWA,
    float* __restrict__ out_f, float* __restrict__ proj_f,
    float* xs, int lane)
{
    constexpr int IN = 16, OUT = 64;
    constexpr int SOFF = SELF_FIRST ? 0 : IN;
    constexpr int AOFF = SELF_FIRST ? IN : 0;
#pragma unroll
    for (int k = lane; k < IN; k += 32) xs[SOFF + k] = self_f[node * IN + k];

    int n = min(cnt[node], CAP);
    const int* lst = list + node * CAP;
    int i0, i1;
    float4 acc4 = gather_agg<16>(other_f, lst, n, lane, i0, i1);
    int v4 = lane & 3, g4 = lane >> 2;
    if (g4 == 0) *reinterpret_cast<float4*>(xs + AOFF + v4 * 4) = acc4;
    __syncwarp();

    // GEMM: lane owns cols 2*lane, 2*lane+1; float2 weight loads, float4 xs broadcasts
    float2 acc = *reinterpret_cast<const float2*>(sB + 2 * lane);
#pragma unroll
    for (int k = 0; k < 32; k += 4) {
        float4 xv = *reinterpret_cast<const float4*>(xs + k);
        float2 w;
        w = *reinterpret_cast<const float2*>(sW + (k    ) * OUT + 2 * lane); acc.x += xv.x * w.x; acc.y += xv.x * w.y;
        w = *reinterpret_cast<const float2*>(sW + (k + 1) * OUT + 2 * lane); acc.x += xv.y * w.x; acc.y += xv.y * w.y;
        w = *reinterpret_cast<const float2*>(sW + (k + 2) * OUT + 2 * lane); acc.x += xv.z * w.x; acc.y += xv.z * w.y;
        w = *reinterpret_cast<const float2*>(sW + (k + 3) * OUT + 2 * lane); acc.x += xv.w * w.x; acc.y += xv.w * w.y;
    }
    acc.x = fmaxf(acc.x, 0.f); acc.y = fmaxf(acc.y, 0.f);
    *reinterpret_cast<float2*>(out_f + node * OUT + 2 * lane) = acc;
    *reinterpret_cast<float2*>(xs + 64 + 2 * lane) = acc;   // y kept in xs[64..127]
    __syncwarp();

    // projection y(64) @ WA -> 16, k-split by 2 across lane halves
    int c = lane & 15, h = lane >> 4;
    float pr = 0.f;
#pragma unroll
    for (int k = 0; k < 32; k += 4) {
        int kk = h * 32 + k;
        float4 xv = *reinterpret_cast<const float4*>(xs + 64 + kk);
        pr += xv.x * sWA[WA64X16(kk,     c)];
        pr += xv.y * sWA[WA64X16(kk + 1, c)];
        pr += xv.z * sWA[WA64X16(kk + 2, c)];
        pr += xv.w * sWA[WA64X16(kk + 3, c)];
    }
    pr += __shfl_down_sync(FULLM, pr, 16);
    if (lane < 16) proj_f[node * 16 + lane] = pr;
    __syncwarp();
}

// ---------------- L3: side-split, grid-stride ----------------
__global__ void __launch_bounds__(256) l3_k(
    const float* __restrict__ wp3, const float* __restrict__ bp3,
    const float* __restrict__ wt3, const float* __restrict__ bt3,
    const float* __restrict__ wp4, const float* __restrict__ wt4)
{
    __shared__ float sW[2048], sWA[1040], sB[64];
    __shared__ __align__(16) float sX[8][128];
    int tid = threadIdx.x, warp = tid >> 5, lane = tid & 31;
    int half = gridDim.x >> 1;
    bool pside = blockIdx.x < half;
    const float* W  = pside ? wp3 : wt3;
    const float* B  = pside ? bp3 : bt3;
    const float* WA = pside ? wt4 : (wp4 + 1024);   // agg part projecting THIS side's output
    ((float4*)sW)[tid]       = ((const float4*)W)[tid];
    ((float4*)sW)[tid + 256] = ((const float4*)W)[tid + 256];
    for (int i = tid; i < 1024; i += 256) {
        int k = i >> 4, c = i & 15;
        sWA[WA64X16(k, c)] = WA[i];
    }
    if (tid < 64) sB[tid] = B[tid];
    __syncthreads();
    int bid = pside ? blockIdx.x : blockIdx.x - half;
    int stride = half * 8;
    if (pside) {
        for (int node = bid * 8 + warp; node < NP; node += stride)
            layer3_proj_node<true >(node, d_pb, d_tb, d_rcnt, d_rlist, sW, sB, sWA, d_pa, d_prt, sX[warp], lane);
    } else {
        for (int node = bid * 8 + warp; node < NT; node += stride)
            layer3_proj_node<false>(node, d_tb, d_pb, d_ccnt, d_clist, sW, sB, sWA, d_ta, d_prp, sX[warp], lane);
    }
}

// ---------------- L4 combine node: k-split GEMM over C=64 ----------------
__device__ __forceinline__ float l4_node(
    int node, const float* __restrict__ self_f, const float* __restrict__ proj_other,
    const int* __restrict__ cnt, const int* __restrict__ list,
    const float* sW, const float* sB, const float* sAC,
    float* xs, int lane, int& n_out, int& i0, int& i1, const int*& lst_out)
{
#pragma unroll
    for (int k = lane; k < 64; k += 32) xs[k] = self_f[node * 64 + k];

    int n = min(cnt[node], CAP);
    const int* lst = list + node * CAP;
    n_out = n; lst_out = lst;
    float4 acc4 = gather_agg<16>(proj_other, lst, n, lane, i0, i1);
    int v4 = lane & 3, g4 = lane >> 2;
    if (g4 == 0) *reinterpret_cast<float4*>(xs + 64 + v4 * 4) = acc4;
    __syncwarp();

    int c = lane & 15, h = lane >> 4;
    float acc = 0.f;
#pragma unroll
    for (int k = 0; k < 32; k += 4) {
        int kk = h * 32 + k;
        float4 xv = *reinterpret_cast<const float4*>(xs + kk);
        acc += xv.x * sW[W64X16(kk,     c)];
        acc += xv.y * sW[W64X16(kk + 1, c)];
        acc += xv.z * sW[W64X16(kk + 2, c)];
        acc += xv.w * sW[W64X16(kk + 3, c)];
    }
    acc += __shfl_down_sync(FULLM, acc, 16);

    float contrib = 0.f;
    if (lane < 16) {
        float a = sB[lane] + xs[64 + lane] + acc;
        contrib = fmaxf(a, 0.f) * sAC[lane];
    }
#pragma unroll
    for (int d = 16; d > 0; d >>= 1)
        contrib += __shfl_down_sync(FULLM, contrib, d);
    __syncwarp();
    return contrib;   // lane 0
}

// ---------------- L4 p-side ----------------
__global__ void __launch_bounds__(256) l4p_k(
    const float* __restrict__ wp4, const float* __restrict__ bp4,
    const float* __restrict__ wac)
{
    __shared__ float sW[1104], sB[16], sAC[16];
    __shared__ __align__(16) float sX[8][80];
    int tid = threadIdx.x, warp = tid >> 5, lane = tid & 31;
    for (int i = tid; i < 1024; i += 256) {
        int k = i >> 4, c = i & 15;
        sW[W64X16(k, c)] = wp4[i];
    }
    if (tid < 16) { sB[tid] = bp4[tid]; sAC[tid] = wac[tid]; }
    __syncthreads();
    int stride = gridDim.x * 8;
    for (int node = blockIdx.x * 8 + warp; node < NP; node += stride) {
        int n, i0, i1; const int* lst;
        float c = l4_node(node, d_pa, d_prp, d_rcnt, d_rlist, sW, sB, sAC, sX[warp], lane, n, i0, i1, lst);
        if (lane == 0) d_lp[node] = c;
    }
}

// ---------------- L4 t-side + logits ----------------
__global__ void __launch_bounds__(256) l4t_logits_k(
    const float* __restrict__ wt4, const float* __restrict__ bt4,
    const float* __restrict__ wac, const float* __restrict__ bac)
{
    __shared__ float sW[1104], sB[16], sAC[16];
    __shared__ __align__(16) float sX[8][80];
    int tid = threadIdx.x, warp = tid >> 5, lane = tid & 31;
    for (int i = tid; i < 1024; i += 256) {
        int k = i >> 4, c = i & 15;
        sW[W64X16(k, c)] = wt4[1024 + i];   // self part (rows 64..127)
    }
    if (tid < 16) { sB[tid] = bt4[tid]; sAC[tid] = wac[16 + tid]; }
    __syncthreads();
    float bias = bac[0];
    int stride = gridDim.x * 8;
    for (int node = blockIdx.x * 8 + warp; node < NT; node += stride) {
        int n, i0, i1; const int* lst;
        float c = l4_node(node, d_ta, d_prt, d_ccnt, d_clist, sW, sB, sAC, sX[warp], lane, n, i0, i1, lst);
        float s = 0.f;
        if (lane < n) s += d_lp[i0];
        if (lane + 32 < n) s += d_lp[i1];
        if (n > 64) {
            for (int e = 64 + lane; __any_sync(FULLM, e < n); e += 32)
                if (e < n) s += d_lp[lst[e]];
        }
#pragma unroll
        for (int d = 16; d > 0; d >>= 1) s += __shfl_down_sync(FULLM, s, d);
        if (lane == 0) d_logits[node] = s + c + bias;
    }
}

// ---------------- softmax + ccnt reset ----------------
__global__ void __launch_bounds__(1024) softmax_k(float* __restrict__ out) {
    __shared__ float sm[1024];
    int tid = threadIdx.x;
    float m = -1e30f;
    for (int i = tid; i < NT; i += 1024) m = fmaxf(m, d_logits[i]);
    sm[tid] = m; __syncthreads();
    for (int s = 512; s > 0; s >>= 1) {
        if (tid < s) sm[tid] = fmaxf(sm[tid], sm[tid + s]);
        __syncthreads();
    }
    float mx = sm[0];
    __syncthreads();
    float s = 0.f;
    for (int i = tid; i < NT; i += 1024) s += __expf(d_logits[i] - mx);
    sm[tid] = s; __syncthreads();
    for (int st = 512; st > 0; st >>= 1) {
        if (tid < st) sm[tid] += sm[tid + st];
        __syncthreads();
    }
    float inv = 1.f / sm[0];
    for (int i = tid; i < NT; i += 1024) {
        out[i] = __expf(d_logits[i] - mx) * inv;
        d_ccnt[i] = 0;                    // reset for next launch
    }
}

// ---------------- launch ----------------
extern "C" void kernel_launch(void* const* d_in, const int* in_sizes, int n_in,
                              void* d_out, int out_size) {
    const float* p    = (const float*)d_in[0];
    const float* t    = (const float*)d_in[1];
    const float* adj  = (const float*)d_in[2];
    const float* w_p1 = (const float*)d_in[3];  const float* b_p1 = (const float*)d_in[4];
    const float* w_t1 = (const float*)d_in[5];  const float* b_t1 = (const float*)d_in[6];
    const float* w_p2 = (const float*)d_in[7];  const float* b_p2 = (const float*)d_in[8];
    const float* w_t2 = (const float*)d_in[9];  const float* b_t2 = (const float*)d_in[10];
    const float* w_p3 = (const float*)d_in[11]; const float* b_p3 = (const float*)d_in[12];
    const float* w_t3 = (const float*)d_in[13]; const float* b_t3 = (const float*)d_in[14];
    const float* w_p4 = (const float*)d_in[15]; const float* b_p4 = (const float*)d_in[16];
    const float* w_t4 = (const float*)d_in[17]; const float* b_t4 = (const float*)d_in[18];
    const float* w_ac = (const float*)d_in[19]; const float* b_ac = (const float*)d_in[20];
    float* out = (float*)d_out;

    build_k<<<NP, 256>>>(adj);
    l1_k<<<2 * NBH, 256>>>(p, t, w_p1, b_p1, w_t1, b_t1);
    l2_k<<<2 * NBH, 256>>>(w_p2, b_p2, w_t2, b_t2);
    l3_k<<<2 * NBH, 256>>>(w_p3, b_p3, w_t3, b_t3, w_p4, w_t4);
    l4p_k<<<NBH, 256>>>(w_p4, b_p4, w_ac);
    l4t_logits_k<<<NBH, 256>>>(w_t4, b_t4, w_ac, b_ac);
    softmax_k<<<1, 1024>>>(out);
}

// round 13
// speedup vs baseline: 1.4335x; 1.0229x over previous
#include <cuda_runtime.h>

#define NP 8192
#define NT 8192
#define CAP 256
#define ROW_F4 (NT/4)
#define FULLM 0xffffffffu
#define HALFN 4096            // node B = node A + HALFN

// ---------------- static scratch ----------------
__device__ __align__(16) float d_pa[NP * 64];
__device__ __align__(16) float d_pb[NP * 64];
__device__ __align__(16) float d_ta[NT * 64];
__device__ __align__(16) float d_tb[NT * 64];
__device__ __align__(16) float d_prp[NT * 16];   // t3 @ wp4_agg (for p-side L4)
__device__ __align__(16) float d_prt[NP * 16];   // p3 @ wt4_agg (for t-side L4)
__device__ float d_lp[NP];
__device__ float d_logits[NT];
__device__ int d_rcnt[NP];
__device__ int d_ccnt[NT];      // zero-init; re-zeroed by softmax kernel each launch
__device__ int d_rlist[NP * CAP];
__device__ int d_clist[NT * CAP];

// padded C=64,OUT=16 weight layout (conflict-free two k-halves)
#define W64X16(k, c) ((k) * 17 + (((k) >> 5) << 4) + (c))
// padded C=64,OUT=16 projection layout
#define WA64X16(k, c) ((k) * 16 + (((k) >> 5) << 4) + (c))

// ---------------- build: block per row, 8 in-flight float4 loads per thread ----------------
__global__ void __launch_bounds__(256) build_k(const float* __restrict__ adj) {
    __shared__ int s_cnt;
    int row = blockIdx.x;
    if (threadIdx.x == 0) s_cnt = 0;
    __syncthreads();

    const float4* a4 = reinterpret_cast<const float4*>(adj) + (size_t)row * ROW_F4 + threadIdx.x;
    float4 v[8];
#pragma unroll
    for (int k = 0; k < 8; k++) v[k] = __ldcs(a4 + k * 256);

#pragma unroll
    for (int k = 0; k < 8; k++) {
        if (v[k].x != 0.f || v[k].y != 0.f || v[k].z != 0.f || v[k].w != 0.f) {
            int jb = (threadIdx.x + k * 256) << 2;
            float vals[4] = {v[k].x, v[k].y, v[k].z, v[k].w};
#pragma unroll
            for (int q = 0; q < 4; q++) {
                if (vals[q] != 0.f) {
                    int j = jb + q;
                    int slot = atomicAdd(&s_cnt, 1);
                    if (slot < CAP) d_rlist[row * CAP + slot] = j;
                    int cs = atomicAdd(&d_ccnt[j], 1);
                    if (cs < CAP) d_clist[j * CAP + cs] = row;
                }
            }
        }
    }
    __syncthreads();
    if (threadIdx.x == 0) d_rcnt[row] = min(s_cnt, CAP);
}

// ---------------- shfl-based neighbor index fetch (e < 64) ----------------
__device__ __forceinline__ int shfl_idx(int e, int i0, int i1) {
    int v = (e & 32) ? i1 : i0;
    return __shfl_sync(FULLM, v, e & 31);
}
__device__ __forceinline__ void add4(float4& a, const float* p) {
    float4 t = *reinterpret_cast<const float4*>(p);
    a.x += t.x; a.y += t.y; a.z += t.z; a.w += t.w;
}

// ---------------- dual-node gather: 4 independent load chains per iteration ----------------
template <int IN>
__device__ __forceinline__ void gather_agg2(
    const float* __restrict__ feat,
    const int* __restrict__ lstA, int nA,
    const int* __restrict__ lstB, int nB,
    int lane, float4& outA, float4& outB,
    int& iA0, int& iA1, int& iB0, int& iB1)
{
    constexpr int V = IN / 4;
    constexpr int G = 32 / V;
    int v = lane % V, g = lane / V;
    iA0 = (lane < nA) ? lstA[lane] : 0;
    iA1 = (lane + 32 < nA) ? lstA[lane + 32] : 0;
    iB0 = (lane < nB) ? lstB[lane] : 0;
    iB1 = (lane + 32 < nB) ? lstB[lane + 32] : 0;
    int nlA = min(nA, 64), nlB = min(nB, 64);
    int iters = (max(nlA, nlB) + G - 1) / G;       // warp-uniform
    float4 a0 = make_float4(0.f, 0.f, 0.f, 0.f);
    float4 a1 = make_float4(0.f, 0.f, 0.f, 0.f);
    float4 b0 = make_float4(0.f, 0.f, 0.f, 0.f);
    float4 b1 = make_float4(0.f, 0.f, 0.f, 0.f);
    int k = 0;
    for (; k + 1 < iters; k += 2) {
        int e0 = g + k * G, e1 = e0 + G;
        int xA0 = shfl_idx(e0, iA0, iA1);
        int xA1 = shfl_idx(e1, iA0, iA1);
        int xB0 = shfl_idx(e0, iB0, iB1);
        int xB1 = shfl_idx(e1, iB0, iB1);
        if (e0 < nlA) add4(a0, feat + xA0 * IN + v * 4);
        if (e1 < nlA) add4(a1, feat + xA1 * IN + v * 4);
        if (e0 < nlB) add4(b0, feat + xB0 * IN + v * 4);
        if (e1 < nlB) add4(b1, feat + xB1 * IN + v * 4);
    }
    if (k < iters) {
        int e0 = g + k * G;
        int xA0 = shfl_idx(e0, iA0, iA1);
        int xB0 = shfl_idx(e0, iB0, iB1);
        if (e0 < nlA) add4(a0, feat + xA0 * IN + v * 4);
        if (e0 < nlB) add4(b0, feat + xB0 * IN + v * 4);
    }
    if (nA > 64) {                                  // rare tails (warp-uniform predicates)
        for (int e = 64 + g; __any_sync(FULLM, e < nA); e += G)
            if (e < nA) add4(a0, feat + lstA[e] * IN + v * 4);
    }
    if (nB > 64) {
        for (int e = 64 + g; __any_sync(FULLM, e < nB); e += G)
            if (e < nB) add4(b0, feat + lstB[e] * IN + v * 4);
    }
    a0.x += a1.x; a0.y += a1.y; a0.z += a1.z; a0.w += a1.w;
    b0.x += b1.x; b0.y += b1.y; b0.z += b1.z; b0.w += b1.w;
#pragma unroll
    for (int d = G / 2; d > 0; d >>= 1) {
        a0.x += __shfl_down_sync(FULLM, a0.x, d * V);
        a0.y += __shfl_down_sync(FULLM, a0.y, d * V);
        a0.z += __shfl_down_sync(FULLM, a0.z, d * V);
        a0.w += __shfl_down_sync(FULLM, a0.w, d * V);
        b0.x += __shfl_down_sync(FULLM, b0.x, d * V);
        b0.y += __shfl_down_sync(FULLM, b0.y, d * V);
        b0.z += __shfl_down_sync(FULLM, b0.z, d * V);
        b0.w += __shfl_down_sync(FULLM, b0.w, d * V);
    }
    outA = a0; outB = b0;
}

// ---------------- k-split column GEMM (padded stride OUT+2) ----------------
template <int C, int OUT>
__device__ __forceinline__ float gemm_kcol(const float* xs, const float* sW, int lane) {
    constexpr int SPLIT = 32 / OUT;
    constexpr int KP = C / SPLIT;
    int col = lane & (OUT - 1);
    int grp = lane / OUT;
    int k0 = grp * KP;
    float acc = 0.f;
#pragma unroll
    for (int k = 0; k < KP; k += 4) {
        float4 xv = *reinterpret_cast<const float4*>(xs + k0 + k);
        acc += xv.x * sW[(k0 + k)     * (OUT + 2) + col];
        acc += xv.y * sW[(k0 + k + 1) * (OUT + 2) + col];
        acc += xv.z * sW[(k0 + k + 2) * (OUT + 2) + col];
        acc += xv.w * sW[(k0 + k + 3) * (OUT + 2) + col];
    }
#pragma unroll
    for (int d = OUT; d < 32; d <<= 1) acc += __shfl_down_sync(FULLM, acc, d);
    return acc;
}

// ---------------- dual-node generic layer (OUT <= 32) ----------------
template <int IN, int OUT, bool SELF_FIRST>
__device__ __forceinline__ void layer_node2(
    int nodeA, int nodeB, const float* __restrict__ self_f, const float* __restrict__ other_f,
    const int* __restrict__ cnt, const int* __restrict__ list,
    const float* sW, const float* sB, float* __restrict__ out_f,
    float* xsA, float* xsB, int lane)
{
    constexpr int C = 2 * IN;
    constexpr int SOFF = SELF_FIRST ? 0 : IN;
    constexpr int AOFF = SELF_FIRST ? IN : 0;
#pragma unroll
    for (int k = lane; k < IN; k += 32) {
        xsA[SOFF + k] = self_f[nodeA * IN + k];
        xsB[SOFF + k] = self_f[nodeB * IN + k];
    }
    int nA = min(cnt[nodeA], CAP), nB = min(cnt[nodeB], CAP);
    const int* lstA = list + nodeA * CAP;
    const int* lstB = list + nodeB * CAP;
    float4 accA, accB; int iA0, iA1, iB0, iB1;
    gather_agg2<IN>(other_f, lstA, nA, lstB, nB, lane, accA, accB, iA0, iA1, iB0, iB1);
    constexpr int V = IN / 4;
    int v = lane % V, g = lane / V;
    if (g == 0) {
        *reinterpret_cast<float4*>(xsA + AOFF + v * 4) = accA;
        *reinterpret_cast<float4*>(xsB + AOFF + v * 4) = accB;
    }
    __syncwarp();
    float aA = gemm_kcol<C, OUT>(xsA, sW, lane);
    float aB = gemm_kcol<C, OUT>(xsB, sW, lane);
    if (lane < OUT) {
        out_f[nodeA * OUT + lane] = fmaxf(aA + sB[lane], 0.f);
        out_f[nodeB * OUT + lane] = fmaxf(aB + sB[lane], 0.f);
    }
    __syncwarp();
}

// ---------------- L1 ----------------
__global__ void __launch_bounds__(256) l1_k(
    const float* __restrict__ p0, const float* __restrict__ t0,
    const float* __restrict__ wp, const float* __restrict__ bp,
    const float* __restrict__ wt, const float* __restrict__ bt)
{
    __shared__ float sW[16 * 10], sB[8];
    __shared__ __align__(16) float sX[8][2][16];
    int tid = threadIdx.x, warp = tid >> 5, lane = tid & 31;
    int half = gridDim.x >> 1;
    bool pside = blockIdx.x < half;
    const float* W = pside ? wp : wt;
    const float* B = pside ? bp : bt;
    if (tid < 128) sW[(tid >> 3) * 10 + (tid & 7)] = W[tid];
    if (tid < 8) sB[tid] = B[tid];
    __syncthreads();
    int bid = pside ? blockIdx.x : blockIdx.x - half;
    int gw = bid * 8 + warp;
    if (pside) layer_node2<8, 8, true >(gw, gw + HALFN, p0, t0, d_rcnt, d_rlist, sW, sB, d_pa, sX[warp][0], sX[warp][1], lane);
    else       layer_node2<8, 8, false>(gw, gw + HALFN, t0, p0, d_ccnt, d_clist, sW, sB, d_ta, sX[warp][0], sX[warp][1], lane);
}

// ---------------- L2 ----------------
__global__ void __launch_bounds__(256) l2_k(
    const float* __restrict__ wp, const float* __restrict__ bp,
    const float* __restrict__ wt, const float* __restrict__ bt)
{
    __shared__ float sW[16 * 18], sB[16];
    __shared__ __align__(16) float sX[8][2][16];
    int tid = threadIdx.x, warp = tid >> 5, lane = tid & 31;
    int half = gridDim.x >> 1;
    bool pside = blockIdx.x < half;
    const float* W = pside ? wp : wt;
    const float* B = pside ? bp : bt;
    if (tid < 256) sW[(tid >> 4) * 18 + (tid & 15)] = W[tid];
    if (tid < 16) sB[tid] = B[tid];
    __syncthreads();
    int bid = pside ? blockIdx.x : blockIdx.x - half;
    int gw = bid * 8 + warp;
    if (pside) layer_node2<8, 16, true >(gw, gw + HALFN, d_pa, d_ta, d_rcnt, d_rlist, sW, sB, d_pb, sX[warp][0], sX[warp][1], lane);
    else       layer_node2<8, 16, false>(gw, gw + HALFN, d_ta, d_pa, d_ccnt, d_clist, sW, sB, d_tb, sX[warp][0], sX[warp][1], lane);
}

// ---------------- L3 per-node GEMM + projection (xs holds concat in [0,32), y in [64,128)) ----------------
__device__ __forceinline__ void l3_math(
    int node, const float* sW, const float* sB, const float* sWA,
    float* __restrict__ out_f, float* __restrict__ proj_f, float* xs, int lane)
{
    constexpr int OUT = 64;
    float2 acc = *reinterpret_cast<const float2*>(sB + 2 * lane);
#pragma unroll
    for (int k = 0; k < 32; k += 4) {
        float4 xv = *reinterpret_cast<const float4*>(xs + k);
        float2 w;
        w = *reinterpret_cast<const float2*>(sW + (k    ) * OUT + 2 * lane); acc.x += xv.x * w.x; acc.y += xv.x * w.y;
        w = *reinterpret_cast<const float2*>(sW + (k + 1) * OUT + 2 * lane); acc.x += xv.y * w.x; acc.y += xv.y * w.y;
        w = *reinterpret_cast<const float2*>(sW + (k + 2) * OUT + 2 * lane); acc.x += xv.z * w.x; acc.y += xv.z * w.y;
        w = *reinterpret_cast<const float2*>(sW + (k + 3) * OUT + 2 * lane); acc.x += xv.w * w.x; acc.y += xv.w * w.y;
    }
    acc.x = fmaxf(acc.x, 0.f); acc.y = fmaxf(acc.y, 0.f);
    *reinterpret_cast<float2*>(out_f + node * OUT + 2 * lane) = acc;
    *reinterpret_cast<float2*>(xs + 64 + 2 * lane) = acc;
    __syncwarp();
    int c = lane & 15, h = lane >> 4;
    float pr = 0.f;
#pragma unroll
    for (int k = 0; k < 32; k += 4) {
        int kk = h * 32 + k;
        float4 xv = *reinterpret_cast<const float4*>(xs + 64 + kk);
        pr += xv.x * sWA[WA64X16(kk,     c)];
        pr += xv.y * sWA[WA64X16(kk + 1, c)];
        pr += xv.z * sWA[WA64X16(kk + 2, c)];
        pr += xv.w * sWA[WA64X16(kk + 3, c)];
    }
    pr += __shfl_down_sync(FULLM, pr, 16);
    if (lane < 16) proj_f[node * 16 + lane] = pr;
    __syncwarp();
}

template <bool SELF_FIRST>
__device__ __forceinline__ void layer3_node2(
    int nodeA, int nodeB, const float* __restrict__ self_f, const float* __restrict__ other_f,
    const int* __restrict__ cnt, const int* __restrict__ list,
    const float* sW, const float* sB, const float* sWA,
    float* __restrict__ out_f, float* __restrict__ proj_f,
    float* xsA, float* xsB, int lane)
{
    constexpr int IN = 16;
    constexpr int SOFF = SELF_FIRST ? 0 : IN;
    constexpr int AOFF = SELF_FIRST ? IN : 0;
#pragma unroll
    for (int k = lane; k < IN; k += 32) {
        xsA[SOFF + k] = self_f[nodeA * IN + k];
        xsB[SOFF + k] = self_f[nodeB * IN + k];
    }
    int nA = min(cnt[nodeA], CAP), nB = min(cnt[nodeB], CAP);
    float4 accA, accB; int iA0, iA1, iB0, iB1;
    gather_agg2<16>(other_f, list + nodeA * CAP, nA, list + nodeB * CAP, nB,
                    lane, accA, accB, iA0, iA1, iB0, iB1);
    int v = lane & 3, g = lane >> 2;
    if (g == 0) {
        *reinterpret_cast<float4*>(xsA + AOFF + v * 4) = accA;
        *reinterpret_cast<float4*>(xsB + AOFF + v * 4) = accB;
    }
    __syncwarp();
    l3_math(nodeA, sW, sB, sWA, out_f, proj_f, xsA, lane);
    l3_math(nodeB, sW, sB, sWA, out_f, proj_f, xsB, lane);
}

__global__ void __launch_bounds__(256) l3_k(
    const float* __restrict__ wp3, const float* __restrict__ bp3,
    const float* __restrict__ wt3, const float* __restrict__ bt3,
    const float* __restrict__ wp4, const float* __restrict__ wt4)
{
    __shared__ float sW[2048], sWA[1040], sB[64];
    __shared__ __align__(16) float sX[8][2][128];
    int tid = threadIdx.x, warp = tid >> 5, lane = tid & 31;
    int half = gridDim.x >> 1;
    bool pside = blockIdx.x < half;
    const float* W  = pside ? wp3 : wt3;
    const float* B  = pside ? bp3 : bt3;
    const float* WA = pside ? wt4 : (wp4 + 1024);
    ((float4*)sW)[tid]       = ((const float4*)W)[tid];
    ((float4*)sW)[tid + 256] = ((const float4*)W)[tid + 256];
    for (int i = tid; i < 1024; i += 256) {
        int k = i >> 4, c = i & 15;
        sWA[WA64X16(k, c)] = WA[i];
    }
    if (tid < 64) sB[tid] = B[tid];
    __syncthreads();
    int bid = pside ? blockIdx.x : blockIdx.x - half;
    int gw = bid * 8 + warp;
    if (pside) layer3_node2<true >(gw, gw + HALFN, d_pb, d_tb, d_rcnt, d_rlist, sW, sB, sWA, d_pa, d_prt, sX[warp][0], sX[warp][1], lane);
    else       layer3_node2<false>(gw, gw + HALFN, d_tb, d_pb, d_ccnt, d_clist, sW, sB, sWA, d_ta, d_prp, sX[warp][0], sX[warp][1], lane);
}

// ---------------- L4 per-node math (xs: self in [0,64), agg in [64,80)) ----------------
__device__ __forceinline__ float l4_math(
    const float* sW, const float* sB, const float* sAC, float* xs, int lane)
{
    int c = lane & 15, h = lane >> 4;
    float acc = 0.f;
#pragma unroll
    for (int k = 0; k < 32; k += 4) {
        int kk = h * 32 + k;
        float4 xv = *reinterpret_cast<const float4*>(xs + kk);
        acc += xv.x * sW[W64X16(kk,     c)];
        acc += xv.y * sW[W64X16(kk + 1, c)];
        acc += xv.z * sW[W64X16(kk + 2, c)];
        acc += xv.w * sW[W64X16(kk + 3, c)];
    }
    acc += __shfl_down_sync(FULLM, acc, 16);
    float contrib = 0.f;
    if (lane < 16) {
        float a = sB[lane] + xs[64 + lane] + acc;
        contrib = fmaxf(a, 0.f) * sAC[lane];
    }
#pragma unroll
    for (int d = 16; d > 0; d >>= 1)
        contrib += __shfl_down_sync(FULLM, contrib, d);
    return contrib;   // lane 0
}

// dual-node L4 front end: gathers + self loads for two nodes
__device__ __forceinline__ void l4_front2(
    int nodeA, int nodeB, const float* __restrict__ self_f, const float* __restrict__ proj_other,
    const int* __restrict__ cnt, const int* __restrict__ list,
    float* xsA, float* xsB, int lane,
    int& nA, int& nB, int& iA0, int& iA1, int& iB0, int& iB1)
{
#pragma unroll
    for (int k = lane; k < 64; k += 32) {
        xsA[k] = self_f[nodeA * 64 + k];
        xsB[k] = self_f[nodeB * 64 + k];
    }
    nA = min(cnt[nodeA], CAP); nB = min(cnt[nodeB], CAP);
    float4 accA, accB;
    gather_agg2<16>(proj_other, list + nodeA * CAP, nA, list + nodeB * CAP, nB,
                    lane, accA, accB, iA0, iA1, iB0, iB1);
    int v = lane & 3, g = lane >> 2;
    if (g == 0) {
        *reinterpret_cast<float4*>(xsA + 64 + v * 4) = accA;
        *reinterpret_cast<float4*>(xsB + 64 + v * 4) = accB;
    }
    __syncwarp();
}

// ---------------- L4 p-side ----------------
__global__ void __launch_bounds__(256) l4p_k(
    const float* __restrict__ wp4, const float* __restrict__ bp4,
    const float* __restrict__ wac)
{
    __shared__ float sW[1104], sB[16], sAC[16];
    __shared__ __align__(16) float sX[8][2][80];
    int tid = threadIdx.x, warp = tid >> 5, lane = tid & 31;
    for (int i = tid; i < 1024; i += 256) {
        int k = i >> 4, c = i & 15;
        sW[W64X16(k, c)] = wp4[i];
    }
    if (tid < 16) { sB[tid] = bp4[tid]; sAC[tid] = wac[tid]; }
    __syncthreads();
    int gw = blockIdx.x * 8 + warp;
    int nodeA = gw, nodeB = gw + HALFN;
    int nA, nB, iA0, iA1, iB0, iB1;
    l4_front2(nodeA, nodeB, d_pa, d_prp, d_rcnt, d_rlist, sX[warp][0], sX[warp][1], lane, nA, nB, iA0, iA1, iB0, iB1);
    float cA = l4_math(sW, sB, sAC, sX[warp][0], lane);
    float cB = l4_math(sW, sB, sAC, sX[warp][1], lane);
    if (lane == 0) { d_lp[nodeA] = cA; d_lp[nodeB] = cB; }
}

// ---------------- L4 t-side + logits ----------------
__global__ void __launch_bounds__(256) l4t_logits_k(
    const float* __restrict__ wt4, const float* __restrict__ bt4,
    const float* __restrict__ wac, const float* __restrict__ bac)
{
    __shared__ float sW[1104], sB[16], sAC[16];
    __shared__ __align__(16) float sX[8][2][80];
    int tid = threadIdx.x, warp = tid >> 5, lane = tid & 31;
    for (int i = tid; i < 1024; i += 256) {
        int k = i >> 4, c = i & 15;
        sW[W64X16(k, c)] = wt4[1024 + i];   // self part (rows 64..127)
    }
    if (tid < 16) { sB[tid] = bt4[tid]; sAC[tid] = wac[16 + tid]; }
    __syncthreads();
    float bias = bac[0];
    int gw = blockIdx.x * 8 + warp;
    int nodeA = gw, nodeB = gw + HALFN;
    int nA, nB, iA0, iA1, iB0, iB1;
    l4_front2(nodeA, nodeB, d_ta, d_prt, d_ccnt, d_clist, sX[warp][0], sX[warp][1], lane, nA, nB, iA0, iA1, iB0, iB1);

    // scalar p-contribution gathers (indices resident in registers) — start loads early
    float sA = 0.f, sBv = 0.f;
    if (lane < nA) sA += d_lp[iA0];
    if (lane + 32 < nA) sA += d_lp[iA1];
    if (lane < nB) sBv += d_lp[iB0];
    if (lane + 32 < nB) sBv += d_lp[iB1];
    if (nA > 64) {
        const int* lstA = d_clist + nodeA * CAP;
        for (int e = 64 + lane; __any_sync(FULLM, e < nA); e += 32)
            if (e < nA) sA += d_lp[lstA[e]];
    }
    if (nB > 64) {
        const int* lstB = d_clist + nodeB * CAP;
        for (int e = 64 + lane; __any_sync(FULLM, e < nB); e += 32)
            if (e < nB) sBv += d_lp[lstB[e]];
    }

    float cA = l4_math(sW, sB, sAC, sX[warp][0], lane);
    float cB = l4_math(sW, sB, sAC, sX[warp][1], lane);
#pragma unroll
    for (int d = 16; d > 0; d >>= 1) {
        sA  += __shfl_down_sync(FULLM, sA, d);
        sBv += __shfl_down_sync(FULLM, sBv, d);
    }
    if (lane == 0) {
        d_logits[nodeA] = sA + cA + bias;
        d_logits[nodeB] = sBv + cB + bias;
    }
}

// ---------------- softmax + ccnt reset ----------------
__global__ void __launch_bounds__(1024) softmax_k(float* __restrict__ out) {
    __shared__ float sm[1024];
    int tid = threadIdx.x;
    float m = -1e30f;
    for (int i = tid; i < NT; i += 1024) m = fmaxf(m, d_logits[i]);
    sm[tid] = m; __syncthreads();
    for (int s = 512; s > 0; s >>= 1) {
        if (tid < s) sm[tid] = fmaxf(sm[tid], sm[tid + s]);
        __syncthreads();
    }
    float mx = sm[0];
    __syncthreads();
    float s = 0.f;
    for (int i = tid; i < NT; i += 1024) s += __expf(d_logits[i] - mx);
    sm[tid] = s; __syncthreads();
    for (int st = 512; st > 0; st >>= 1) {
        if (tid < st) sm[tid] += sm[tid + st];
        __syncthreads();
    }
    float inv = 1.f / sm[0];
    for (int i = tid; i < NT; i += 1024) {
        out[i] = __expf(d_logits[i] - mx) * inv;
        d_ccnt[i] = 0;                    // reset for next launch
    }
}

// ---------------- launch ----------------
extern "C" void kernel_launch(void* const* d_in, const int* in_sizes, int n_in,
                              void* d_out, int out_size) {
    const float* p    = (const float*)d_in[0];
    const float* t    = (const float*)d_in[1];
    const float* adj  = (const float*)d_in[2];
    const float* w_p1 = (const float*)d_in[3];  const float* b_p1 = (const float*)d_in[4];
    const float* w_t1 = (const float*)d_in[5];  const float* b_t1 = (const float*)d_in[6];
    const float* w_p2 = (const float*)d_in[7];  const float* b_p2 = (const float*)d_in[8];
    const float* w_t2 = (const float*)d_in[9];  const float* b_t2 = (const float*)d_in[10];
    const float* w_p3 = (const float*)d_in[11]; const float* b_p3 = (const float*)d_in[12];
    const float* w_t3 = (const float*)d_in[13]; const float* b_t3 = (const float*)d_in[14];
    const float* w_p4 = (const float*)d_in[15]; const float* b_p4 = (const float*)d_in[16];
    const float* w_t4 = (const float*)d_in[17]; const float* b_t4 = (const float*)d_in[18];
    const float* w_ac = (const float*)d_in[19]; const float* b_ac = (const float*)d_in[20];
    float* out = (float*)d_out;

    build_k<<<NP, 256>>>(adj);
    l1_k<<<1024, 256>>>(p, t, w_p1, b_p1, w_t1, b_t1);   // 512 blocks/side, 2 nodes/warp
    l2_k<<<1024, 256>>>(w_p2, b_p2, w_t2, b_t2);
    l3_k<<<1024, 256>>>(w_p3, b_p3, w_t3, b_t3, w_p4, w_t4);
    l4p_k<<<512, 256>>>(w_p4, b_p4, w_ac);
    l4t_logits_k<<<512, 256>>>(w_t4, b_t4, w_ac, b_ac);
    softmax_k<<<1, 1024>>>(out);
}